// round 1
// baseline (speedup 1.0000x reference)
#include <cuda_runtime.h>
#include <math.h>

// Problem constants
#define BB 4
#define LL 1024
#define DD 768
#define EE 32
#define SS 32
#define HH 3072
#define KK 1024   // E*S

// ---------------- device scratch (no allocations allowed) ----------------
__device__ float g_xn[BB * LL * DD];          // 12.6 MB
__device__ float g_phin[DD * KK];             // 3.1 MB
__device__ float g_logits[BB * LL * KK];      // 16.8 MB
__device__ float g_dw[BB * LL * KK];          // 16.8 MB
__device__ float g_cw[BB * LL * KK];          // 16.8 MB
__device__ float g_slots[BB * KK * DD];       // 12.6 MB
__device__ float g_h[BB * KK * HH];           // 50.3 MB
__device__ float g_eo[BB * KK * DD];          // 12.6 MB

// ---------------- row L2 normalize: x [4096,768] ----------------
__global__ void norm_x_kernel(const float* __restrict__ x, float* __restrict__ out) {
    int row = blockIdx.x;
    const float* p = x + (size_t)row * DD;
    float s = 0.f;
    for (int i = threadIdx.x; i < DD; i += 256) { float v = p[i]; s += v * v; }
    __shared__ float sm[8];
    for (int o = 16; o; o >>= 1) s += __shfl_xor_sync(0xffffffffu, s, o);
    if ((threadIdx.x & 31) == 0) sm[threadIdx.x >> 5] = s;
    __syncthreads();
    float tot = 0.f;
#pragma unroll
    for (int i = 0; i < 8; i++) tot += sm[i];
    float inv = 1.f / fmaxf(sqrtf(tot), 1e-12f);
    float* o2 = out + (size_t)row * DD;
    for (int i = threadIdx.x; i < DD; i += 256) o2[i] = p[i] * inv;
}

// ---------------- column L2 normalize: phi [768,1024] over dim 0, * scale ----
__global__ void norm_phi_kernel(const float* __restrict__ phi,
                                const float* __restrict__ scale,
                                float* __restrict__ out) {
    int k = blockIdx.x;  // 0..1023
    float s = 0.f;
    for (int d = threadIdx.x; d < DD; d += 256) { float v = phi[(size_t)d * KK + k]; s += v * v; }
    __shared__ float sm[8];
    for (int o = 16; o; o >>= 1) s += __shfl_xor_sync(0xffffffffu, s, o);
    if ((threadIdx.x & 31) == 0) sm[threadIdx.x >> 5] = s;
    __syncthreads();
    float tot = 0.f;
#pragma unroll
    for (int i = 0; i < 8; i++) tot += sm[i];
    float inv = scale[0] / fmaxf(sqrtf(tot), 1e-12f);
    for (int d = threadIdx.x; d < DD; d += 256) out[(size_t)d * KK + k] = phi[(size_t)d * KK + k] * inv;
}

// ---------------- fused dual softmax over rows of 1024 ----------------
// d_w: softmax within each warp's 32 contiguous values (slot group)
// c_w: softmax over the whole 1024-element row
__global__ void softmax_kernel(const float* __restrict__ logits,
                               float* __restrict__ dw, float* __restrict__ cw) {
    int row = blockIdx.x;
    size_t base = (size_t)row * KK;
    int tid = threadIdx.x, lane = tid & 31, wid = tid >> 5;
    float v = logits[base + tid];
    // group (warp) softmax
    float gmax = v;
    for (int o = 16; o; o >>= 1) gmax = fmaxf(gmax, __shfl_xor_sync(0xffffffffu, gmax, o));
    float ge = expf(v - gmax);
    float gsum = ge;
    for (int o = 16; o; o >>= 1) gsum += __shfl_xor_sync(0xffffffffu, gsum, o);
    dw[base + tid] = ge / gsum;
    // row softmax
    __shared__ float wmax[32], wsum[32];
    __shared__ float s_rmax, s_rsum;
    if (lane == 0) wmax[wid] = gmax;
    __syncthreads();
    if (tid < 32) {
        float m = wmax[tid];
        for (int o = 16; o; o >>= 1) m = fmaxf(m, __shfl_xor_sync(0xffffffffu, m, o));
        if (tid == 0) s_rmax = m;
    }
    __syncthreads();
    float e2 = expf(v - s_rmax);
    float ws = e2;
    for (int o = 16; o; o >>= 1) ws += __shfl_xor_sync(0xffffffffu, ws, o);
    if (lane == 0) wsum[wid] = ws;
    __syncthreads();
    if (tid < 32) {
        float t = wsum[tid];
        for (int o = 16; o; o >>= 1) t += __shfl_xor_sync(0xffffffffu, t, o);
        if (tid == 0) s_rsum = t;
    }
    __syncthreads();
    cw[base + tid] = e2 / s_rsum;
}

// ---------------- generic batched 128x128x8 SGEMM, arbitrary A strides ------
// C[z][m][n] = sum_k A[z*batchA + m*sAm + k*sAk] * B[z*batchB + k*sBk + n]
// C row-major, row stride N. All M,N multiples of 128; K multiple of 8.
__global__ void __launch_bounds__(256) sgemm_kernel(
    const float* __restrict__ A, const float* __restrict__ B, float* __restrict__ C,
    int M, int N, int K,
    long sAm, long sAk, long batchA,
    long sBk, long batchB, long batchC) {
    __shared__ float As[8][132];
    __shared__ float Bs[8][128];
    const float* Ab = A + (size_t)blockIdx.z * batchA;
    const float* Bbp = B + (size_t)blockIdx.z * batchB;
    float* Cb = C + (size_t)blockIdx.z * batchC;
    int m0 = blockIdx.y * 128, n0 = blockIdx.x * 128;
    int tid = threadIdx.x;
    int ty = tid >> 4, tx = tid & 15;
    float acc[8][8];
#pragma unroll
    for (int i = 0; i < 8; i++)
#pragma unroll
        for (int j = 0; j < 8; j++) acc[i][j] = 0.f;
    bool akmaj = (sAk == 1);
    for (int k0 = 0; k0 < K; k0 += 8) {
#pragma unroll
        for (int i = 0; i < 4; i++) {
            int idx = tid + i * 256;
            int mk, kk;
            if (akmaj) { mk = idx >> 3; kk = idx & 7; }
            else       { mk = idx & 127; kk = idx >> 7; }
            As[kk][mk] = Ab[(size_t)(m0 + mk) * sAm + (size_t)(k0 + kk) * sAk];
            int nn = idx & 127, kb = idx >> 7;
            Bs[kb][nn] = Bbp[(size_t)(k0 + kb) * sBk + (n0 + nn)];
        }
        __syncthreads();
#pragma unroll
        for (int k = 0; k < 8; k++) {
            float a[8], b[8];
            *(float4*)(a)     = *(const float4*)&As[k][ty * 4];
            *(float4*)(a + 4) = *(const float4*)&As[k][ty * 4 + 64];
            *(float4*)(b)     = *(const float4*)&Bs[k][tx * 4];
            *(float4*)(b + 4) = *(const float4*)&Bs[k][tx * 4 + 64];
#pragma unroll
            for (int i = 0; i < 8; i++)
#pragma unroll
                for (int j = 0; j < 8; j++) acc[i][j] += a[i] * b[j];
        }
        __syncthreads();
    }
#pragma unroll
    for (int i = 0; i < 8; i++) {
        int m = m0 + ((i < 4) ? (ty * 4 + i) : (64 + ty * 4 + i - 4));
        float4 v0 = make_float4(acc[i][0], acc[i][1], acc[i][2], acc[i][3]);
        float4 v1 = make_float4(acc[i][4], acc[i][5], acc[i][6], acc[i][7]);
        *(float4*)&Cb[(size_t)m * N + n0 + tx * 4] = v0;
        *(float4*)&Cb[(size_t)m * N + n0 + 64 + tx * 4] = v1;
    }
}

// ---------------- expert SGEMM: M=128 rows gathered as (b, e*32+s) ----------
// A row r (0..127): offset (r>>5)*aBatch + (e*32 + (r&31))*K   (row-major, len K)
// B: per-expert [K,N] at B + e*K*N. bias per-expert [N]. Optional exact GELU.
template <bool GELU>
__global__ void __launch_bounds__(256) sgemm_expert_kernel(
    const float* __restrict__ A, const float* __restrict__ B,
    const float* __restrict__ bias, float* __restrict__ C,
    int N, int K, long aBatch, long cBatch) {
    int e = blockIdx.z;
    __shared__ float As[8][132];
    __shared__ float Bs[8][128];
    const float* Be = B + (size_t)e * K * N;
    const float* biasE = bias + (size_t)e * N;
    int n0 = blockIdx.x * 128;
    int tid = threadIdx.x;
    int ty = tid >> 4, tx = tid & 15;
    float acc[8][8];
#pragma unroll
    for (int i = 0; i < 8; i++)
#pragma unroll
        for (int j = 0; j < 8; j++) acc[i][j] = 0.f;
    for (int k0 = 0; k0 < K; k0 += 8) {
#pragma unroll
        for (int i = 0; i < 4; i++) {
            int idx = tid + i * 256;
            int mk = idx >> 3, kk = idx & 7;
            size_t off = (size_t)(mk >> 5) * aBatch + (size_t)(e * 32 + (mk & 31)) * K;
            As[kk][mk] = A[off + k0 + kk];
            int nn = idx & 127, kb = idx >> 7;
            Bs[kb][nn] = Be[(size_t)(k0 + kb) * N + n0 + nn];
        }
        __syncthreads();
#pragma unroll
        for (int k = 0; k < 8; k++) {
            float a[8], b[8];
            *(float4*)(a)     = *(const float4*)&As[k][ty * 4];
            *(float4*)(a + 4) = *(const float4*)&As[k][ty * 4 + 64];
            *(float4*)(b)     = *(const float4*)&Bs[k][tx * 4];
            *(float4*)(b + 4) = *(const float4*)&Bs[k][tx * 4 + 64];
#pragma unroll
            for (int i = 0; i < 8; i++)
#pragma unroll
                for (int j = 0; j < 8; j++) acc[i][j] += a[i] * b[j];
        }
        __syncthreads();
    }
#pragma unroll
    for (int i = 0; i < 8; i++) {
        int m = (i < 4) ? (ty * 4 + i) : (64 + ty * 4 + i - 4);
        size_t coff = (size_t)(m >> 5) * cBatch + (size_t)(e * 32 + (m & 31)) * N;
#pragma unroll
        for (int half = 0; half < 2; half++) {
            int nb = n0 + half * 64 + tx * 4;
            float4 v;
            float vv[4];
#pragma unroll
            for (int j = 0; j < 4; j++) {
                float xv = acc[i][half * 4 + j] + biasE[nb + j];
                if (GELU) xv = xv * normcdff(xv);
                vv[j] = xv;
            }
            v = make_float4(vv[0], vv[1], vv[2], vv[3]);
            *(float4*)&C[coff + nb] = v;
        }
    }
}

// ---------------- host launcher ----------------
extern "C" void kernel_launch(void* const* d_in, const int* in_sizes, int n_in,
                              void* d_out, int out_size) {
    const float* x     = (const float*)d_in[0];  // [4,1024,768]
    const float* phi   = (const float*)d_in[1];  // [768,32,32]
    const float* scale = (const float*)d_in[2];  // [1]
    const float* w1    = (const float*)d_in[3];  // [32,768,3072]
    const float* b1    = (const float*)d_in[4];  // [32,3072]
    const float* w2    = (const float*)d_in[5];  // [32,3072,768]
    const float* b2    = (const float*)d_in[6];  // [32,768]
    float* out = (float*)d_out;                  // [4,1024,768]

    float *xn, *phin, *logits, *dw, *cw, *slots, *h, *eo;
    cudaGetSymbolAddress((void**)&xn, g_xn);
    cudaGetSymbolAddress((void**)&phin, g_phin);
    cudaGetSymbolAddress((void**)&logits, g_logits);
    cudaGetSymbolAddress((void**)&dw, g_dw);
    cudaGetSymbolAddress((void**)&cw, g_cw);
    cudaGetSymbolAddress((void**)&slots, g_slots);
    cudaGetSymbolAddress((void**)&h, g_h);
    cudaGetSymbolAddress((void**)&eo, g_eo);

    // 1) normalize x rows -> xn [4096,768]
    norm_x_kernel<<<BB * LL, 256>>>(x, xn);
    // 2) normalize phi columns (dim 0) * scale -> phin [768,1024]
    norm_phi_kernel<<<KK, 256>>>(phi, scale, phin);
    // 3) logits [4096,1024] = xn @ phin
    sgemm_kernel<<<dim3(KK / 128, (BB * LL) / 128, 1), 256>>>(
        xn, phin, logits, BB * LL, KK, DD,
        (long)DD, 1L, 0L,
        (long)KK, 0L, 0L);
    // 4) softmaxes
    softmax_kernel<<<BB * LL, 1024>>>(logits, dw, cw);
    // 5) slots[b] [1024,768] = dw[b]^T @ xn[b]
    sgemm_kernel<<<dim3(DD / 128, KK / 128, BB), 256>>>(
        dw, xn, slots, KK, DD, LL,
        1L, (long)KK, (long)(LL * KK),
        (long)DD, (long)(LL * DD), (long)(KK * DD));
    // 6) h = gelu(slots @ w1 + b1)   (per expert, M = B*S = 128)
    sgemm_expert_kernel<true><<<dim3(HH / 128, 1, EE), 256>>>(
        slots, w1, b1, h, HH, DD, (long)(KK * DD), (long)(KK * HH));
    // 7) eo = h @ w2 + b2
    sgemm_expert_kernel<false><<<dim3(DD / 128, 1, EE), 256>>>(
        h, w2, b2, eo, DD, HH, (long)(KK * HH), (long)(KK * DD));
    // 8) out[b] [1024,768] = cw[b] @ eo[b]
    sgemm_kernel<<<dim3(DD / 128, LL / 128, BB), 256>>>(
        cw, eo, out, LL, DD, KK,
        (long)KK, 1L, (long)(LL * KK),
        (long)DD, (long)(KK * DD), (long)(LL * DD));
}

// round 3
// speedup vs baseline: 1.3202x; 1.3202x over previous
#include <cuda_runtime.h>
#include <math.h>

// Problem constants
#define BB 4
#define LL 1024
#define DD 768
#define EE 32
#define SS 32
#define HH 3072
#define KK 1024   // E*S

// ---------------- device scratch (no allocations allowed) ----------------
__device__ float g_xn[BB * LL * DD];
__device__ float g_phin[DD * KK];
__device__ float g_logits[BB * LL * KK];
__device__ float g_dw[BB * LL * KK];
__device__ float g_cw[BB * LL * KK];
__device__ float g_slots[BB * KK * DD];
__device__ float g_h[BB * KK * HH];
__device__ float g_eo[BB * KK * DD];

// ---------------- tf32 helpers ----------------
__device__ __forceinline__ void split_tf32(float x, float& hi, float& lo) {
    unsigned u;
    asm("cvt.rna.tf32.f32 %0, %1;" : "=r"(u) : "f"(x));
    hi = __uint_as_float(u);
    float r = x - hi;
    unsigned ul;
    asm("cvt.rna.tf32.f32 %0, %1;" : "=r"(ul) : "f"(r));
    lo = __uint_as_float(ul);
}

__device__ __forceinline__ void mma_tf32(float* d, const unsigned* a, const unsigned* b) {
    asm volatile(
        "mma.sync.aligned.m16n8k8.row.col.f32.tf32.tf32.f32 "
        "{%0,%1,%2,%3}, {%4,%5,%6,%7}, {%8,%9}, {%0,%1,%2,%3};\n"
        : "+f"(d[0]), "+f"(d[1]), "+f"(d[2]), "+f"(d[3])
        : "r"(a[0]), "r"(a[1]), "r"(a[2]), "r"(a[3]), "r"(b[0]), "r"(b[1]));
}

// ---------------- row L2 normalize: x [4096,768] ----------------
__global__ void norm_x_kernel(const float* __restrict__ x, float* __restrict__ out) {
    int row = blockIdx.x;
    const float* p = x + (size_t)row * DD;
    float s = 0.f;
    for (int i = threadIdx.x; i < DD; i += 256) { float v = p[i]; s += v * v; }
    __shared__ float sm[8];
    for (int o = 16; o; o >>= 1) s += __shfl_xor_sync(0xffffffffu, s, o);
    if ((threadIdx.x & 31) == 0) sm[threadIdx.x >> 5] = s;
    __syncthreads();
    float tot = 0.f;
#pragma unroll
    for (int i = 0; i < 8; i++) tot += sm[i];
    float inv = 1.f / fmaxf(sqrtf(tot), 1e-12f);
    float* o2 = out + (size_t)row * DD;
    for (int i = threadIdx.x; i < DD; i += 256) o2[i] = p[i] * inv;
}

// ---------------- column L2 normalize: phi over dim 0, * scale ----
__global__ void norm_phi_kernel(const float* __restrict__ phi,
                                const float* __restrict__ scale,
                                float* __restrict__ out) {
    int k = blockIdx.x;
    float s = 0.f;
    for (int d = threadIdx.x; d < DD; d += 256) { float v = phi[(size_t)d * KK + k]; s += v * v; }
    __shared__ float sm[8];
    for (int o = 16; o; o >>= 1) s += __shfl_xor_sync(0xffffffffu, s, o);
    if ((threadIdx.x & 31) == 0) sm[threadIdx.x >> 5] = s;
    __syncthreads();
    float tot = 0.f;
#pragma unroll
    for (int i = 0; i < 8; i++) tot += sm[i];
    float inv = scale[0] / fmaxf(sqrtf(tot), 1e-12f);
    for (int d = threadIdx.x; d < DD; d += 256) out[(size_t)d * KK + k] = phi[(size_t)d * KK + k] * inv;
}

// ---------------- fused dual softmax over rows of 1024 ----------------
__global__ void softmax_kernel(const float* __restrict__ logits,
                               float* __restrict__ dw, float* __restrict__ cw) {
    int row = blockIdx.x;
    size_t base = (size_t)row * KK;
    int tid = threadIdx.x, lane = tid & 31, wid = tid >> 5;
    float v = logits[base + tid];
    float gmax = v;
    for (int o = 16; o; o >>= 1) gmax = fmaxf(gmax, __shfl_xor_sync(0xffffffffu, gmax, o));
    float ge = expf(v - gmax);
    float gsum = ge;
    for (int o = 16; o; o >>= 1) gsum += __shfl_xor_sync(0xffffffffu, gsum, o);
    dw[base + tid] = ge / gsum;
    __shared__ float wmax[32], wsum[32];
    __shared__ float s_rmax, s_rsum;
    if (lane == 0) wmax[wid] = gmax;
    __syncthreads();
    if (tid < 32) {
        float m = wmax[tid];
        for (int o = 16; o; o >>= 1) m = fmaxf(m, __shfl_xor_sync(0xffffffffu, m, o));
        if (tid == 0) s_rmax = m;
    }
    __syncthreads();
    float e2 = expf(v - s_rmax);
    float ws = e2;
    for (int o = 16; o; o >>= 1) ws += __shfl_xor_sync(0xffffffffu, ws, o);
    if (lane == 0) wsum[wid] = ws;
    __syncthreads();
    if (tid < 32) {
        float t = wsum[tid];
        for (int o = 16; o; o >>= 1) t += __shfl_xor_sync(0xffffffffu, t, o);
        if (tid == 0) s_rsum = t;
    }
    __syncthreads();
    cw[base + tid] = e2 / s_rsum;
}

// ================= tensor-core tf32x3 GEMM (128x128 block, Ktile=16) ========
// C[z][m][n] = sum_k A[...] * B[...]; M,N mult of 128, K mult of 16.
#define PITCH 136

struct SmemGemm {
    float As_hi[16][PITCH];
    float As_lo[16][PITCH];
    float Bs_hi[16][PITCH];
    float Bs_lo[16][PITCH];
};

template <bool AKMAJ>
__global__ void __launch_bounds__(256) tc_gemm_kernel(
    const float* __restrict__ A, const float* __restrict__ B, float* __restrict__ C,
    int M, int N, int K,
    long sAm, long sAk, long batchA,
    long sBk, long batchB, long batchC) {
    __shared__ SmemGemm sm;
    const float* Ab = A + (size_t)blockIdx.z * batchA;
    const float* Bb = B + (size_t)blockIdx.z * batchB;
    float* Cb = C + (size_t)blockIdx.z * batchC;
    int m0 = blockIdx.y * 128, n0 = blockIdx.x * 128;
    int tid = threadIdx.x, lane = tid & 31, wid = tid >> 5;
    int warp_m = wid >> 2, warp_n = wid & 3;   // 2 x 4
    int g = lane >> 2, tig = lane & 3;

    float acc[4][4][4];
#pragma unroll
    for (int a = 0; a < 4; a++)
#pragma unroll
        for (int b = 0; b < 4; b++)
#pragma unroll
            for (int c = 0; c < 4; c++) acc[a][b][c] = 0.f;

    float regA[8], regB[8];
    int KT = K >> 4;

    // prologue: load tile 0
#pragma unroll
    for (int i = 0; i < 8; i++) {
        int idx = i * 256 + tid;
        int m, k;
        if (AKMAJ) { m = idx >> 4; k = idx & 15; } else { m = idx & 127; k = idx >> 7; }
        regA[i] = Ab[(size_t)(m0 + m) * sAm + (size_t)k * sAk];
        int kb = idx >> 7, n = idx & 127;
        regB[i] = Bb[(size_t)kb * sBk + n0 + n];
    }
#pragma unroll
    for (int i = 0; i < 8; i++) {
        int idx = i * 256 + tid;
        int m, k;
        if (AKMAJ) { m = idx >> 4; k = idx & 15; } else { m = idx & 127; k = idx >> 7; }
        float hi, lo;
        split_tf32(regA[i], hi, lo);
        sm.As_hi[k][m] = hi; sm.As_lo[k][m] = lo;
        int kb = idx >> 7, n = idx & 127;
        split_tf32(regB[i], hi, lo);
        sm.Bs_hi[kb][n] = hi; sm.Bs_lo[kb][n] = lo;
    }
    __syncthreads();

    for (int kt = 0; kt < KT; kt++) {
        int k0n = (kt + 1) << 4;
        bool has_next = (kt + 1) < KT;
        if (has_next) {
#pragma unroll
            for (int i = 0; i < 8; i++) {
                int idx = i * 256 + tid;
                int m, k;
                if (AKMAJ) { m = idx >> 4; k = idx & 15; } else { m = idx & 127; k = idx >> 7; }
                regA[i] = Ab[(size_t)(m0 + m) * sAm + (size_t)(k0n + k) * sAk];
                int kb = idx >> 7, n = idx & 127;
                regB[i] = Bb[(size_t)(k0n + kb) * sBk + n0 + n];
            }
        }
#pragma unroll
        for (int ks = 0; ks < 2; ks++) {
            unsigned aHi[4][4], aLo[4][4], bHi[4][2], bLo[4][2];
#pragma unroll
            for (int mt = 0; mt < 4; mt++) {
                int r = warp_m * 64 + mt * 16 + g;
                int c = ks * 8 + tig;
                aHi[mt][0] = __float_as_uint(sm.As_hi[c][r]);
                aHi[mt][1] = __float_as_uint(sm.As_hi[c][r + 8]);
                aHi[mt][2] = __float_as_uint(sm.As_hi[c + 4][r]);
                aHi[mt][3] = __float_as_uint(sm.As_hi[c + 4][r + 8]);
                aLo[mt][0] = __float_as_uint(sm.As_lo[c][r]);
                aLo[mt][1] = __float_as_uint(sm.As_lo[c][r + 8]);
                aLo[mt][2] = __float_as_uint(sm.As_lo[c + 4][r]);
                aLo[mt][3] = __float_as_uint(sm.As_lo[c + 4][r + 8]);
            }
#pragma unroll
            for (int nt = 0; nt < 4; nt++) {
                int col = warp_n * 32 + nt * 8 + g;
                int kr = ks * 8 + tig;
                bHi[nt][0] = __float_as_uint(sm.Bs_hi[kr][col]);
                bHi[nt][1] = __float_as_uint(sm.Bs_hi[kr + 4][col]);
                bLo[nt][0] = __float_as_uint(sm.Bs_lo[kr][col]);
                bLo[nt][1] = __float_as_uint(sm.Bs_lo[kr + 4][col]);
            }
#pragma unroll
            for (int mt = 0; mt < 4; mt++)
#pragma unroll
                for (int nt = 0; nt < 4; nt++) {
                    mma_tf32(acc[mt][nt], aHi[mt], bLo[nt]);
                    mma_tf32(acc[mt][nt], aLo[mt], bHi[nt]);
                    mma_tf32(acc[mt][nt], aHi[mt], bHi[nt]);
                }
        }
        __syncthreads();
        if (has_next) {
#pragma unroll
            for (int i = 0; i < 8; i++) {
                int idx = i * 256 + tid;
                int m, k;
                if (AKMAJ) { m = idx >> 4; k = idx & 15; } else { m = idx & 127; k = idx >> 7; }
                float hi, lo;
                split_tf32(regA[i], hi, lo);
                sm.As_hi[k][m] = hi; sm.As_lo[k][m] = lo;
                int kb = idx >> 7, n = idx & 127;
                split_tf32(regB[i], hi, lo);
                sm.Bs_hi[kb][n] = hi; sm.Bs_lo[kb][n] = lo;
            }
            __syncthreads();
        }
    }

    // epilogue
#pragma unroll
    for (int mt = 0; mt < 4; mt++)
#pragma unroll
        for (int nt = 0; nt < 4; nt++) {
            int r = m0 + warp_m * 64 + mt * 16 + g;
            int c = n0 + warp_n * 32 + nt * 8 + tig * 2;
            float2 v0 = make_float2(acc[mt][nt][0], acc[mt][nt][1]);
            float2 v1 = make_float2(acc[mt][nt][2], acc[mt][nt][3]);
            *(float2*)&Cb[(size_t)r * N + c] = v0;
            *(float2*)&Cb[(size_t)(r + 8) * N + c] = v1;
        }
}

// ---- expert GEMM: M=128 gathered rows (b*32slots), per-expert B + bias (+GELU)
template <bool GELU>
__global__ void __launch_bounds__(256) tc_gemm_expert_kernel(
    const float* __restrict__ A, const float* __restrict__ B,
    const float* __restrict__ bias, float* __restrict__ C,
    int N, int K, long aBatch, long cBatch) {
    __shared__ SmemGemm sm;
    int e = blockIdx.z;
    const float* Be = B + (size_t)e * K * N;
    const float* biasE = bias + (size_t)e * N;
    int n0 = blockIdx.x * 128;
    int tid = threadIdx.x, lane = tid & 31, wid = tid >> 5;
    int warp_m = wid >> 2, warp_n = wid & 3;
    int g = lane >> 2, tig = lane & 3;

    float acc[4][4][4];
#pragma unroll
    for (int a = 0; a < 4; a++)
#pragma unroll
        for (int b = 0; b < 4; b++)
#pragma unroll
            for (int c = 0; c < 4; c++) acc[a][b][c] = 0.f;

    float regA[8], regB[8];
    int KT = K >> 4;

#pragma unroll
    for (int i = 0; i < 8; i++) {
        int idx = i * 256 + tid;
        int m = idx >> 4, k = idx & 15;
        size_t off = (size_t)(m >> 5) * aBatch + (size_t)(e * 32 + (m & 31)) * K;
        regA[i] = A[off + k];
        int kb = idx >> 7, n = idx & 127;
        regB[i] = Be[(size_t)kb * N + n0 + n];
    }
#pragma unroll
    for (int i = 0; i < 8; i++) {
        int idx = i * 256 + tid;
        int m = idx >> 4, k = idx & 15;
        float hi, lo;
        split_tf32(regA[i], hi, lo);
        sm.As_hi[k][m] = hi; sm.As_lo[k][m] = lo;
        int kb = idx >> 7, n = idx & 127;
        split_tf32(regB[i], hi, lo);
        sm.Bs_hi[kb][n] = hi; sm.Bs_lo[kb][n] = lo;
    }
    __syncthreads();

    for (int kt = 0; kt < KT; kt++) {
        int k0n = (kt + 1) << 4;
        bool has_next = (kt + 1) < KT;
        if (has_next) {
#pragma unroll
            for (int i = 0; i < 8; i++) {
                int idx = i * 256 + tid;
                int m = idx >> 4, k = idx & 15;
                size_t off = (size_t)(m >> 5) * aBatch + (size_t)(e * 32 + (m & 31)) * K;
                regA[i] = A[off + k0n + k];
                int kb = idx >> 7, n = idx & 127;
                regB[i] = Be[(size_t)(k0n + kb) * N + n0 + n];
            }
        }
#pragma unroll
        for (int ks = 0; ks < 2; ks++) {
            unsigned aHi[4][4], aLo[4][4], bHi[4][2], bLo[4][2];
#pragma unroll
            for (int mt = 0; mt < 4; mt++) {
                int r = warp_m * 64 + mt * 16 + g;
                int c = ks * 8 + tig;
                aHi[mt][0] = __float_as_uint(sm.As_hi[c][r]);
                aHi[mt][1] = __float_as_uint(sm.As_hi[c][r + 8]);
                aHi[mt][2] = __float_as_uint(sm.As_hi[c + 4][r]);
                aHi[mt][3] = __float_as_uint(sm.As_hi[c + 4][r + 8]);
                aLo[mt][0] = __float_as_uint(sm.As_lo[c][r]);
                aLo[mt][1] = __float_as_uint(sm.As_lo[c][r + 8]);
                aLo[mt][2] = __float_as_uint(sm.As_lo[c + 4][r]);
                aLo[mt][3] = __float_as_uint(sm.As_lo[c + 4][r + 8]);
            }
#pragma unroll
            for (int nt = 0; nt < 4; nt++) {
                int col = warp_n * 32 + nt * 8 + g;
                int kr = ks * 8 + tig;
                bHi[nt][0] = __float_as_uint(sm.Bs_hi[kr][col]);
                bHi[nt][1] = __float_as_uint(sm.Bs_hi[kr + 4][col]);
                bLo[nt][0] = __float_as_uint(sm.Bs_lo[kr][col]);
                bLo[nt][1] = __float_as_uint(sm.Bs_lo[kr + 4][col]);
            }
#pragma unroll
            for (int mt = 0; mt < 4; mt++)
#pragma unroll
                for (int nt = 0; nt < 4; nt++) {
                    mma_tf32(acc[mt][nt], aHi[mt], bLo[nt]);
                    mma_tf32(acc[mt][nt], aLo[mt], bHi[nt]);
                    mma_tf32(acc[mt][nt], aHi[mt], bHi[nt]);
                }
        }
        __syncthreads();
        if (has_next) {
#pragma unroll
            for (int i = 0; i < 8; i++) {
                int idx = i * 256 + tid;
                int m = idx >> 4, k = idx & 15;
                float hi, lo;
                split_tf32(regA[i], hi, lo);
                sm.As_hi[k][m] = hi; sm.As_lo[k][m] = lo;
                int kb = idx >> 7, n = idx & 127;
                split_tf32(regB[i], hi, lo);
                sm.Bs_hi[kb][n] = hi; sm.Bs_lo[kb][n] = lo;
            }
            __syncthreads();
        }
    }

#pragma unroll
    for (int mt = 0; mt < 4; mt++)
#pragma unroll
        for (int nt = 0; nt < 4; nt++) {
            int m = warp_m * 64 + mt * 16 + g;
            int c = n0 + warp_n * 32 + nt * 8 + tig * 2;
            float2 bb = *(const float2*)&biasE[c];
#pragma unroll
            for (int half = 0; half < 2; half++) {
                int mm = m + half * 8;
                size_t coff = (size_t)(mm >> 5) * cBatch + (size_t)(e * 32 + (mm & 31)) * N;
                float v0 = acc[mt][nt][half * 2 + 0] + bb.x;
                float v1 = acc[mt][nt][half * 2 + 1] + bb.y;
                if (GELU) { v0 = v0 * normcdff(v0); v1 = v1 * normcdff(v1); }
                *(float2*)&C[coff + c] = make_float2(v0, v1);
            }
        }
}

// ---------------- host launcher ----------------
extern "C" void kernel_launch(void* const* d_in, const int* in_sizes, int n_in,
                              void* d_out, int out_size) {
    const float* x     = (const float*)d_in[0];
    const float* phi   = (const float*)d_in[1];
    const float* scale = (const float*)d_in[2];
    const float* w1    = (const float*)d_in[3];
    const float* b1    = (const float*)d_in[4];
    const float* w2    = (const float*)d_in[5];
    const float* b2    = (const float*)d_in[6];
    float* out = (float*)d_out;

    float *xn, *phin, *logits, *dw, *cw, *slots, *h, *eo;
    cudaGetSymbolAddress((void**)&xn, g_xn);
    cudaGetSymbolAddress((void**)&phin, g_phin);
    cudaGetSymbolAddress((void**)&logits, g_logits);
    cudaGetSymbolAddress((void**)&dw, g_dw);
    cudaGetSymbolAddress((void**)&cw, g_cw);
    cudaGetSymbolAddress((void**)&slots, g_slots);
    cudaGetSymbolAddress((void**)&h, g_h);
    cudaGetSymbolAddress((void**)&eo, g_eo);

    // 1) normalize x rows -> xn [4096,768]
    norm_x_kernel<<<BB * LL, 256>>>(x, xn);
    // 2) normalize phi columns * scale -> phin [768,1024]
    norm_phi_kernel<<<KK, 256>>>(phi, scale, phin);
    // 3) logits [4096,1024] = xn @ phin   (A k-major)
    tc_gemm_kernel<true><<<dim3(KK / 128, (BB * LL) / 128, 1), 256>>>(
        xn, phin, logits, BB * LL, KK, DD,
        (long)DD, 1L, 0L,
        (long)KK, 0L, 0L);
    // 4) softmaxes
    softmax_kernel<<<BB * LL, 1024>>>(logits, dw, cw);
    // 5) slots[b] [1024,768] = dw[b]^T @ xn[b]   (A m-major)
    tc_gemm_kernel<false><<<dim3(DD / 128, KK / 128, BB), 256>>>(
        dw, xn, slots, KK, DD, LL,
        1L, (long)KK, (long)(LL * KK),
        (long)DD, (long)(LL * DD), (long)(KK * DD));
    // 6) h = gelu(slots @ w1 + b1)
    tc_gemm_expert_kernel<true><<<dim3(HH / 128, 1, EE), 256>>>(
        slots, w1, b1, h, HH, DD, (long)(KK * DD), (long)(KK * HH));
    // 7) eo = h @ w2 + b2
    tc_gemm_expert_kernel<false><<<dim3(DD / 128, 1, EE), 256>>>(
        h, w2, b2, eo, DD, HH, (long)(KK * HH), (long)(KK * DD));
    // 8) out[b] [1024,768] = cw[b] @ eo[b]   (A k-major)
    tc_gemm_kernel<true><<<dim3(DD / 128, LL / 128, BB), 256>>>(
        cw, eo, out, LL, DD, KK,
        (long)KK, 1L, (long)(LL * KK),
        (long)DD, (long)(KK * DD), (long)(LL * DD));
}

// round 4
// speedup vs baseline: 1.8742x; 1.4196x over previous
#include <cuda_runtime.h>
#include <cuda_bf16.h>
#include <math.h>

// Problem constants
#define BB 4
#define LL 1024
#define DD 768
#define EE 32
#define SS 32
#define HH 3072
#define KK 1024   // E*S

// ---------------- device scratch (no allocations allowed) ----------------
__device__ float g_xn[BB * LL * DD];
__device__ float g_phin[DD * KK];
__device__ float g_logits[BB * LL * KK];
__device__ float g_dw[BB * LL * KK];
__device__ float g_cw[BB * LL * KK];
__device__ float g_slots[BB * KK * DD];
__device__ float g_h[BB * KK * HH];
__device__ float g_eo[BB * KK * DD];

// ---------------- tf32 helpers ----------------
__device__ __forceinline__ void split_tf32(float x, float& hi, float& lo) {
    unsigned u;
    asm("cvt.rna.tf32.f32 %0, %1;" : "=r"(u) : "f"(x));
    hi = __uint_as_float(u);
    float r = x - hi;
    unsigned ul;
    asm("cvt.rna.tf32.f32 %0, %1;" : "=r"(ul) : "f"(r));
    lo = __uint_as_float(ul);
}

__device__ __forceinline__ void mma_tf32(float* d, const unsigned* a, const unsigned* b) {
    asm volatile(
        "mma.sync.aligned.m16n8k8.row.col.f32.tf32.tf32.f32 "
        "{%0,%1,%2,%3}, {%4,%5,%6,%7}, {%8,%9}, {%0,%1,%2,%3};\n"
        : "+f"(d[0]), "+f"(d[1]), "+f"(d[2]), "+f"(d[3])
        : "r"(a[0]), "r"(a[1]), "r"(a[2]), "r"(a[3]), "r"(b[0]), "r"(b[1]));
}

// ---------------- bf16 helpers ----------------
__device__ __forceinline__ void split_bf16_pack(float x0, float x1, unsigned& hi, unsigned& lo) {
    __nv_bfloat16 h0 = __float2bfloat16_rn(x0);
    __nv_bfloat16 l0 = __float2bfloat16_rn(x0 - __bfloat162float(h0));
    __nv_bfloat16 h1 = __float2bfloat16_rn(x1);
    __nv_bfloat16 l1 = __float2bfloat16_rn(x1 - __bfloat162float(h1));
    hi = ((unsigned)__bfloat16_as_ushort(h1) << 16) | (unsigned)__bfloat16_as_ushort(h0);
    lo = ((unsigned)__bfloat16_as_ushort(l1) << 16) | (unsigned)__bfloat16_as_ushort(l0);
}

__device__ __forceinline__ void mma_bf16(float* d, const unsigned* a, const unsigned* b) {
    asm volatile(
        "mma.sync.aligned.m16n8k16.row.col.f32.bf16.bf16.f32 "
        "{%0,%1,%2,%3}, {%4,%5,%6,%7}, {%8,%9}, {%0,%1,%2,%3};\n"
        : "+f"(d[0]), "+f"(d[1]), "+f"(d[2]), "+f"(d[3])
        : "r"(a[0]), "r"(a[1]), "r"(a[2]), "r"(a[3]), "r"(b[0]), "r"(b[1]));
}

// ---------------- row L2 normalize: x [4096,768] ----------------
__global__ void norm_x_kernel(const float* __restrict__ x, float* __restrict__ out) {
    int row = blockIdx.x;
    const float* p = x + (size_t)row * DD;
    float s = 0.f;
    for (int i = threadIdx.x; i < DD; i += 256) { float v = p[i]; s += v * v; }
    __shared__ float sm[8];
    for (int o = 16; o; o >>= 1) s += __shfl_xor_sync(0xffffffffu, s, o);
    if ((threadIdx.x & 31) == 0) sm[threadIdx.x >> 5] = s;
    __syncthreads();
    float tot = 0.f;
#pragma unroll
    for (int i = 0; i < 8; i++) tot += sm[i];
    float inv = 1.f / fmaxf(sqrtf(tot), 1e-12f);
    float* o2 = out + (size_t)row * DD;
    for (int i = threadIdx.x; i < DD; i += 256) o2[i] = p[i] * inv;
}

// ---------------- column L2 normalize: phi over dim 0, * scale ----
__global__ void norm_phi_kernel(const float* __restrict__ phi,
                                const float* __restrict__ scale,
                                float* __restrict__ out) {
    int k = blockIdx.x;
    float s = 0.f;
    for (int d = threadIdx.x; d < DD; d += 256) { float v = phi[(size_t)d * KK + k]; s += v * v; }
    __shared__ float sm[8];
    for (int o = 16; o; o >>= 1) s += __shfl_xor_sync(0xffffffffu, s, o);
    if ((threadIdx.x & 31) == 0) sm[threadIdx.x >> 5] = s;
    __syncthreads();
    float tot = 0.f;
#pragma unroll
    for (int i = 0; i < 8; i++) tot += sm[i];
    float inv = scale[0] / fmaxf(sqrtf(tot), 1e-12f);
    for (int d = threadIdx.x; d < DD; d += 256) out[(size_t)d * KK + k] = phi[(size_t)d * KK + k] * inv;
}

// ---------------- fused dual softmax over rows of 1024 ----------------
__global__ void softmax_kernel(const float* __restrict__ logits,
                               float* __restrict__ dw, float* __restrict__ cw) {
    int row = blockIdx.x;
    size_t base = (size_t)row * KK;
    int tid = threadIdx.x, lane = tid & 31, wid = tid >> 5;
    float v = logits[base + tid];
    float gmax = v;
    for (int o = 16; o; o >>= 1) gmax = fmaxf(gmax, __shfl_xor_sync(0xffffffffu, gmax, o));
    float ge = expf(v - gmax);
    float gsum = ge;
    for (int o = 16; o; o >>= 1) gsum += __shfl_xor_sync(0xffffffffu, gsum, o);
    dw[base + tid] = ge / gsum;
    __shared__ float wmax[32], wsum[32];
    __shared__ float s_rmax, s_rsum;
    if (lane == 0) wmax[wid] = gmax;
    __syncthreads();
    if (tid < 32) {
        float m = wmax[tid];
        for (int o = 16; o; o >>= 1) m = fmaxf(m, __shfl_xor_sync(0xffffffffu, m, o));
        if (tid == 0) s_rmax = m;
    }
    __syncthreads();
    float e2 = expf(v - s_rmax);
    float ws = e2;
    for (int o = 16; o; o >>= 1) ws += __shfl_xor_sync(0xffffffffu, ws, o);
    if (lane == 0) wsum[wid] = ws;
    __syncthreads();
    if (tid < 32) {
        float t = wsum[tid];
        for (int o = 16; o; o >>= 1) t += __shfl_xor_sync(0xffffffffu, t, o);
        if (tid == 0) s_rsum = t;
    }
    __syncthreads();
    cw[base + tid] = e2 / s_rsum;
}

// ================= tf32x3 GEMM (128x128 block, Ktile=16) =====================
#define PITCH 136

struct SmemGemm {
    float As_hi[16][PITCH];
    float As_lo[16][PITCH];
    float Bs_hi[16][PITCH];
    float Bs_lo[16][PITCH];
};

template <bool AKMAJ>
__global__ void __launch_bounds__(256) tc_gemm_kernel(
    const float* __restrict__ A, const float* __restrict__ B, float* __restrict__ C,
    int M, int N, int K,
    long sAm, long sAk, long batchA,
    long sBk, long batchB, long batchC) {
    __shared__ SmemGemm sm;
    const float* Ab = A + (size_t)blockIdx.z * batchA;
    const float* Bb = B + (size_t)blockIdx.z * batchB;
    float* Cb = C + (size_t)blockIdx.z * batchC;
    int m0 = blockIdx.y * 128, n0 = blockIdx.x * 128;
    int tid = threadIdx.x, lane = tid & 31, wid = tid >> 5;
    int warp_m = wid >> 2, warp_n = wid & 3;
    int g = lane >> 2, tig = lane & 3;

    float acc[4][4][4];
#pragma unroll
    for (int a = 0; a < 4; a++)
#pragma unroll
        for (int b = 0; b < 4; b++)
#pragma unroll
            for (int c = 0; c < 4; c++) acc[a][b][c] = 0.f;

    float regA[8], regB[8];
    int KT = K >> 4;

#pragma unroll
    for (int i = 0; i < 8; i++) {
        int idx = i * 256 + tid;
        int m, k;
        if (AKMAJ) { m = idx >> 4; k = idx & 15; } else { m = idx & 127; k = idx >> 7; }
        regA[i] = Ab[(size_t)(m0 + m) * sAm + (size_t)k * sAk];
        int kb = idx >> 7, n = idx & 127;
        regB[i] = Bb[(size_t)kb * sBk + n0 + n];
    }
#pragma unroll
    for (int i = 0; i < 8; i++) {
        int idx = i * 256 + tid;
        int m, k;
        if (AKMAJ) { m = idx >> 4; k = idx & 15; } else { m = idx & 127; k = idx >> 7; }
        float hi, lo;
        split_tf32(regA[i], hi, lo);
        sm.As_hi[k][m] = hi; sm.As_lo[k][m] = lo;
        int kb = idx >> 7, n = idx & 127;
        split_tf32(regB[i], hi, lo);
        sm.Bs_hi[kb][n] = hi; sm.Bs_lo[kb][n] = lo;
    }
    __syncthreads();

    for (int kt = 0; kt < KT; kt++) {
        int k0n = (kt + 1) << 4;
        bool has_next = (kt + 1) < KT;
        if (has_next) {
#pragma unroll
            for (int i = 0; i < 8; i++) {
                int idx = i * 256 + tid;
                int m, k;
                if (AKMAJ) { m = idx >> 4; k = idx & 15; } else { m = idx & 127; k = idx >> 7; }
                regA[i] = Ab[(size_t)(m0 + m) * sAm + (size_t)(k0n + k) * sAk];
                int kb = idx >> 7, n = idx & 127;
                regB[i] = Bb[(size_t)(k0n + kb) * sBk + n0 + n];
            }
        }
#pragma unroll
        for (int ks = 0; ks < 2; ks++) {
            unsigned aHi[4][4], aLo[4][4], bHi[4][2], bLo[4][2];
#pragma unroll
            for (int mt = 0; mt < 4; mt++) {
                int r = warp_m * 64 + mt * 16 + g;
                int c = ks * 8 + tig;
                aHi[mt][0] = __float_as_uint(sm.As_hi[c][r]);
                aHi[mt][1] = __float_as_uint(sm.As_hi[c][r + 8]);
                aHi[mt][2] = __float_as_uint(sm.As_hi[c + 4][r]);
                aHi[mt][3] = __float_as_uint(sm.As_hi[c + 4][r + 8]);
                aLo[mt][0] = __float_as_uint(sm.As_lo[c][r]);
                aLo[mt][1] = __float_as_uint(sm.As_lo[c][r + 8]);
                aLo[mt][2] = __float_as_uint(sm.As_lo[c + 4][r]);
                aLo[mt][3] = __float_as_uint(sm.As_lo[c + 4][r + 8]);
            }
#pragma unroll
            for (int nt = 0; nt < 4; nt++) {
                int col = warp_n * 32 + nt * 8 + g;
                int kr = ks * 8 + tig;
                bHi[nt][0] = __float_as_uint(sm.Bs_hi[kr][col]);
                bHi[nt][1] = __float_as_uint(sm.Bs_hi[kr + 4][col]);
                bLo[nt][0] = __float_as_uint(sm.Bs_lo[kr][col]);
                bLo[nt][1] = __float_as_uint(sm.Bs_lo[kr + 4][col]);
            }
#pragma unroll
            for (int mt = 0; mt < 4; mt++)
#pragma unroll
                for (int nt = 0; nt < 4; nt++) {
                    mma_tf32(acc[mt][nt], aHi[mt], bLo[nt]);
                    mma_tf32(acc[mt][nt], aLo[mt], bHi[nt]);
                    mma_tf32(acc[mt][nt], aHi[mt], bHi[nt]);
                }
        }
        __syncthreads();
        if (has_next) {
#pragma unroll
            for (int i = 0; i < 8; i++) {
                int idx = i * 256 + tid;
                int m, k;
                if (AKMAJ) { m = idx >> 4; k = idx & 15; } else { m = idx & 127; k = idx >> 7; }
                float hi, lo;
                split_tf32(regA[i], hi, lo);
                sm.As_hi[k][m] = hi; sm.As_lo[k][m] = lo;
                int kb = idx >> 7, n = idx & 127;
                split_tf32(regB[i], hi, lo);
                sm.Bs_hi[kb][n] = hi; sm.Bs_lo[kb][n] = lo;
            }
            __syncthreads();
        }
    }

#pragma unroll
    for (int mt = 0; mt < 4; mt++)
#pragma unroll
        for (int nt = 0; nt < 4; nt++) {
            int r = m0 + warp_m * 64 + mt * 16 + g;
            int c = n0 + warp_n * 32 + nt * 8 + tig * 2;
            float2 v0 = make_float2(acc[mt][nt][0], acc[mt][nt][1]);
            float2 v1 = make_float2(acc[mt][nt][2], acc[mt][nt][3]);
            *(float2*)&Cb[(size_t)r * N + c] = v0;
            *(float2*)&Cb[(size_t)(r + 8) * N + c] = v1;
        }
}

// ================= bf16x3 GEMM (128x128 block, Ktile=32) =====================
// Smem planes hold packed bf16x2 pairs along k: plane[k2][m] = (k=2*k2, k=2*k2+1)
#define BPITCH 136

struct SmemB16 {
    unsigned Ah[16][BPITCH];
    unsigned Al[16][BPITCH];
    unsigned Bh[16][BPITCH];
    unsigned Bl[16][BPITCH];
};

// fragment loads for m16n8k16 at k-pair base hk (0 or 8 within the 32-k tile)
__device__ __forceinline__ void bf16_frags_a(const unsigned (*P)[BPITCH], int hk, int r, int tig, unsigned* a) {
    a[0] = P[hk + tig][r];
    a[1] = P[hk + tig][r + 8];
    a[2] = P[hk + tig + 4][r];
    a[3] = P[hk + tig + 4][r + 8];
}
__device__ __forceinline__ void bf16_frags_b(const unsigned (*P)[BPITCH], int hk, int col, int tig, unsigned* b) {
    b[0] = P[hk + tig][col];
    b[1] = P[hk + tig + 4][col];
}

template <bool AKMAJ>
__global__ void __launch_bounds__(256) bf16_gemm_kernel(
    const float* __restrict__ A, const float* __restrict__ B, float* __restrict__ C,
    int M, int N, int K,
    long sAm, long sAk, long batchA,
    long sBk, long batchB, long batchC) {
    __shared__ SmemB16 sm;
    const float* Ab = A + (size_t)blockIdx.z * batchA;
    const float* Bb = B + (size_t)blockIdx.z * batchB;
    float* Cb = C + (size_t)blockIdx.z * batchC;
    int m0 = blockIdx.y * 128, n0 = blockIdx.x * 128;
    int tid = threadIdx.x, lane = tid & 31, wid = tid >> 5;
    int warp_m = wid >> 2, warp_n = wid & 3;
    int g = lane >> 2, tig = lane & 3;

    float acc[4][4][4];
#pragma unroll
    for (int a = 0; a < 4; a++)
#pragma unroll
        for (int b = 0; b < 4; b++)
#pragma unroll
            for (int c = 0; c < 4; c++) acc[a][b][c] = 0.f;

    float rA0[8], rA1[8], rB0[8], rB1[8];
    int KT = K >> 5;

    // prologue: load tile 0 (2048 bf16x2 slots per operand, 8 per thread)
#pragma unroll
    for (int i = 0; i < 8; i++) {
        int idx = i * 256 + tid;
        if (AKMAJ) {
            int m = idx >> 4, k2 = idx & 15;
            float2 v = *(const float2*)&Ab[(size_t)(m0 + m) * sAm + (size_t)(2 * k2)];
            rA0[i] = v.x; rA1[i] = v.y;
        } else {
            int m = idx & 127, k2 = idx >> 7;
            size_t o = (size_t)(m0 + m) * sAm + (size_t)(2 * k2) * sAk;
            rA0[i] = Ab[o]; rA1[i] = Ab[o + sAk];
        }
        int n = idx & 127, k2b = idx >> 7;
        size_t ob = (size_t)(2 * k2b) * sBk + (n0 + n);
        rB0[i] = Bb[ob]; rB1[i] = Bb[ob + sBk];
    }
#pragma unroll
    for (int i = 0; i < 8; i++) {
        int idx = i * 256 + tid;
        int m, k2;
        if (AKMAJ) { m = idx >> 4; k2 = idx & 15; } else { m = idx & 127; k2 = idx >> 7; }
        unsigned hi, lo;
        split_bf16_pack(rA0[i], rA1[i], hi, lo);
        sm.Ah[k2][m] = hi; sm.Al[k2][m] = lo;
        int n = idx & 127, k2b = idx >> 7;
        split_bf16_pack(rB0[i], rB1[i], hi, lo);
        sm.Bh[k2b][n] = hi; sm.Bl[k2b][n] = lo;
    }
    __syncthreads();

    for (int kt = 0; kt < KT; kt++) {
        int k0n = (kt + 1) << 5;
        bool has_next = (kt + 1) < KT;
        if (has_next) {
#pragma unroll
            for (int i = 0; i < 8; i++) {
                int idx = i * 256 + tid;
                if (AKMAJ) {
                    int m = idx >> 4, k2 = idx & 15;
                    float2 v = *(const float2*)&Ab[(size_t)(m0 + m) * sAm + (size_t)(k0n + 2 * k2)];
                    rA0[i] = v.x; rA1[i] = v.y;
                } else {
                    int m = idx & 127, k2 = idx >> 7;
                    size_t o = (size_t)(m0 + m) * sAm + (size_t)(k0n + 2 * k2) * sAk;
                    rA0[i] = Ab[o]; rA1[i] = Ab[o + sAk];
                }
                int n = idx & 127, k2b = idx >> 7;
                size_t ob = (size_t)(k0n + 2 * k2b) * sBk + (n0 + n);
                rB0[i] = Bb[ob]; rB1[i] = Bb[ob + sBk];
            }
        }
#pragma unroll
        for (int ks = 0; ks < 2; ks++) {
            int hk = ks * 8;
            unsigned aHi[4][4], aLo[4][4], bHi[4][2], bLo[4][2];
#pragma unroll
            for (int mt = 0; mt < 4; mt++) {
                int r = warp_m * 64 + mt * 16 + g;
                bf16_frags_a(sm.Ah, hk, r, tig, aHi[mt]);
                bf16_frags_a(sm.Al, hk, r, tig, aLo[mt]);
            }
#pragma unroll
            for (int nt = 0; nt < 4; nt++) {
                int col = warp_n * 32 + nt * 8 + g;
                bf16_frags_b(sm.Bh, hk, col, tig, bHi[nt]);
                bf16_frags_b(sm.Bl, hk, col, tig, bLo[nt]);
            }
#pragma unroll
            for (int mt = 0; mt < 4; mt++)
#pragma unroll
                for (int nt = 0; nt < 4; nt++) {
                    mma_bf16(acc[mt][nt], aHi[mt], bLo[nt]);
                    mma_bf16(acc[mt][nt], aLo[mt], bHi[nt]);
                    mma_bf16(acc[mt][nt], aHi[mt], bHi[nt]);
                }
        }
        __syncthreads();
        if (has_next) {
#pragma unroll
            for (int i = 0; i < 8; i++) {
                int idx = i * 256 + tid;
                int m, k2;
                if (AKMAJ) { m = idx >> 4; k2 = idx & 15; } else { m = idx & 127; k2 = idx >> 7; }
                unsigned hi, lo;
                split_bf16_pack(rA0[i], rA1[i], hi, lo);
                sm.Ah[k2][m] = hi; sm.Al[k2][m] = lo;
                int n = idx & 127, k2b = idx >> 7;
                split_bf16_pack(rB0[i], rB1[i], hi, lo);
                sm.Bh[k2b][n] = hi; sm.Bl[k2b][n] = lo;
            }
            __syncthreads();
        }
    }

#pragma unroll
    for (int mt = 0; mt < 4; mt++)
#pragma unroll
        for (int nt = 0; nt < 4; nt++) {
            int r = m0 + warp_m * 64 + mt * 16 + g;
            int c = n0 + warp_n * 32 + nt * 8 + tig * 2;
            float2 v0 = make_float2(acc[mt][nt][0], acc[mt][nt][1]);
            float2 v1 = make_float2(acc[mt][nt][2], acc[mt][nt][3]);
            *(float2*)&Cb[(size_t)r * N + c] = v0;
            *(float2*)&Cb[(size_t)(r + 8) * N + c] = v1;
        }
}

// ---- bf16x3 expert GEMM: M=128 gathered rows, per-expert B + bias (+GELU) ---
template <bool GELU>
__global__ void __launch_bounds__(256) bf16_gemm_expert_kernel(
    const float* __restrict__ A, const float* __restrict__ B,
    const float* __restrict__ bias, float* __restrict__ C,
    int N, int K, long aBatch, long cBatch) {
    __shared__ SmemB16 sm;
    int e = blockIdx.z;
    const float* Be = B + (size_t)e * K * N;
    const float* biasE = bias + (size_t)e * N;
    int n0 = blockIdx.x * 128;
    int tid = threadIdx.x, lane = tid & 31, wid = tid >> 5;
    int warp_m = wid >> 2, warp_n = wid & 3;
    int g = lane >> 2, tig = lane & 3;

    float acc[4][4][4];
#pragma unroll
    for (int a = 0; a < 4; a++)
#pragma unroll
        for (int b = 0; b < 4; b++)
#pragma unroll
            for (int c = 0; c < 4; c++) acc[a][b][c] = 0.f;

    float rA0[8], rA1[8], rB0[8], rB1[8];
    int KT = K >> 5;

#pragma unroll
    for (int i = 0; i < 8; i++) {
        int idx = i * 256 + tid;
        int m = idx >> 4, k2 = idx & 15;
        size_t off = (size_t)(m >> 5) * aBatch + (size_t)(e * 32 + (m & 31)) * K;
        float2 v = *(const float2*)&A[off + 2 * k2];
        rA0[i] = v.x; rA1[i] = v.y;
        int n = idx & 127, k2b = idx >> 7;
        size_t ob = (size_t)(2 * k2b) * N + n0 + n;
        rB0[i] = Be[ob]; rB1[i] = Be[ob + N];
    }
#pragma unroll
    for (int i = 0; i < 8; i++) {
        int idx = i * 256 + tid;
        int m = idx >> 4, k2 = idx & 15;
        unsigned hi, lo;
        split_bf16_pack(rA0[i], rA1[i], hi, lo);
        sm.Ah[k2][m] = hi; sm.Al[k2][m] = lo;
        int n = idx & 127, k2b = idx >> 7;
        split_bf16_pack(rB0[i], rB1[i], hi, lo);
        sm.Bh[k2b][n] = hi; sm.Bl[k2b][n] = lo;
    }
    __syncthreads();

    for (int kt = 0; kt < KT; kt++) {
        int k0n = (kt + 1) << 5;
        bool has_next = (kt + 1) < KT;
        if (has_next) {
#pragma unroll
            for (int i = 0; i < 8; i++) {
                int idx = i * 256 + tid;
                int m = idx >> 4, k2 = idx & 15;
                size_t off = (size_t)(m >> 5) * aBatch + (size_t)(e * 32 + (m & 31)) * K;
                float2 v = *(const float2*)&A[off + k0n + 2 * k2];
                rA0[i] = v.x; rA1[i] = v.y;
                int n = idx & 127, k2b = idx >> 7;
                size_t ob = (size_t)(k0n + 2 * k2b) * N + n0 + n;
                rB0[i] = Be[ob]; rB1[i] = Be[ob + N];
            }
        }
#pragma unroll
        for (int ks = 0; ks < 2; ks++) {
            int hk = ks * 8;
            unsigned aHi[4][4], aLo[4][4], bHi[4][2], bLo[4][2];
#pragma unroll
            for (int mt = 0; mt < 4; mt++) {
                int r = warp_m * 64 + mt * 16 + g;
                bf16_frags_a(sm.Ah, hk, r, tig, aHi[mt]);
                bf16_frags_a(sm.Al, hk, r, tig, aLo[mt]);
            }
#pragma unroll
            for (int nt = 0; nt < 4; nt++) {
                int col = warp_n * 32 + nt * 8 + g;
                bf16_frags_b(sm.Bh, hk, col, tig, bHi[nt]);
                bf16_frags_b(sm.Bl, hk, col, tig, bLo[nt]);
            }
#pragma unroll
            for (int mt = 0; mt < 4; mt++)
#pragma unroll
                for (int nt = 0; nt < 4; nt++) {
                    mma_bf16(acc[mt][nt], aHi[mt], bLo[nt]);
                    mma_bf16(acc[mt][nt], aLo[mt], bHi[nt]);
                    mma_bf16(acc[mt][nt], aHi[mt], bHi[nt]);
                }
        }
        __syncthreads();
        if (has_next) {
#pragma unroll
            for (int i = 0; i < 8; i++) {
                int idx = i * 256 + tid;
                int m = idx >> 4, k2 = idx & 15;
                unsigned hi, lo;
                split_bf16_pack(rA0[i], rA1[i], hi, lo);
                sm.Ah[k2][m] = hi; sm.Al[k2][m] = lo;
                int n = idx & 127, k2b = idx >> 7;
                split_bf16_pack(rB0[i], rB1[i], hi, lo);
                sm.Bh[k2b][n] = hi; sm.Bl[k2b][n] = lo;
            }
            __syncthreads();
        }
    }

#pragma unroll
    for (int mt = 0; mt < 4; mt++)
#pragma unroll
        for (int nt = 0; nt < 4; nt++) {
            int m = warp_m * 64 + mt * 16 + g;
            int c = n0 + warp_n * 32 + nt * 8 + tig * 2;
            float2 bb = *(const float2*)&biasE[c];
#pragma unroll
            for (int half = 0; half < 2; half++) {
                int mm = m + half * 8;
                size_t coff = (size_t)(mm >> 5) * cBatch + (size_t)(e * 32 + (mm & 31)) * N;
                float v0 = acc[mt][nt][half * 2 + 0] + bb.x;
                float v1 = acc[mt][nt][half * 2 + 1] + bb.y;
                if (GELU) { v0 = v0 * normcdff(v0); v1 = v1 * normcdff(v1); }
                *(float2*)&C[coff + c] = make_float2(v0, v1);
            }
        }
}

// ---------------- host launcher ----------------
extern "C" void kernel_launch(void* const* d_in, const int* in_sizes, int n_in,
                              void* d_out, int out_size) {
    const float* x     = (const float*)d_in[0];
    const float* phi   = (const float*)d_in[1];
    const float* scale = (const float*)d_in[2];
    const float* w1    = (const float*)d_in[3];
    const float* b1    = (const float*)d_in[4];
    const float* w2    = (const float*)d_in[5];
    const float* b2    = (const float*)d_in[6];
    float* out = (float*)d_out;

    float *xn, *phin, *logits, *dw, *cw, *slots, *h, *eo;
    cudaGetSymbolAddress((void**)&xn, g_xn);
    cudaGetSymbolAddress((void**)&phin, g_phin);
    cudaGetSymbolAddress((void**)&logits, g_logits);
    cudaGetSymbolAddress((void**)&dw, g_dw);
    cudaGetSymbolAddress((void**)&cw, g_cw);
    cudaGetSymbolAddress((void**)&slots, g_slots);
    cudaGetSymbolAddress((void**)&h, g_h);
    cudaGetSymbolAddress((void**)&eo, g_eo);

    // 1) normalize x rows -> xn [4096,768]
    norm_x_kernel<<<BB * LL, 256>>>(x, xn);
    // 2) normalize phi columns * scale -> phin [768,1024]
    norm_phi_kernel<<<KK, 256>>>(phi, scale, phin);
    // 3) logits [4096,1024] = xn @ phin   (tf32x3, A k-major)
    tc_gemm_kernel<true><<<dim3(KK / 128, (BB * LL) / 128, 1), 256>>>(
        xn, phin, logits, BB * LL, KK, DD,
        (long)DD, 1L, 0L,
        (long)KK, 0L, 0L);
    // 4) softmaxes
    softmax_kernel<<<BB * LL, 1024>>>(logits, dw, cw);
    // 5) slots[b] [1024,768] = dw[b]^T @ xn[b]   (bf16x3, A m-major)
    bf16_gemm_kernel<false><<<dim3(DD / 128, KK / 128, BB), 256>>>(
        dw, xn, slots, KK, DD, LL,
        1L, (long)KK, (long)(LL * KK),
        (long)DD, (long)(LL * DD), (long)(KK * DD));
    // 6) h = gelu(slots @ w1 + b1)   (bf16x3)
    bf16_gemm_expert_kernel<true><<<dim3(HH / 128, 1, EE), 256>>>(
        slots, w1, b1, h, HH, DD, (long)(KK * DD), (long)(KK * HH));
    // 7) eo = h @ w2 + b2   (bf16x3)
    bf16_gemm_expert_kernel<false><<<dim3(DD / 128, 1, EE), 256>>>(
        h, w2, b2, eo, DD, HH, (long)(KK * HH), (long)(KK * DD));
    // 8) out[b] [1024,768] = cw[b] @ eo[b]   (tf32x3, A k-major)
    tc_gemm_kernel<true><<<dim3(DD / 128, LL / 128, BB), 256>>>(
        cw, eo, out, LL, DD, KK,
        (long)KK, 1L, (long)(LL * KK),
        (long)DD, (long)(KK * DD), (long)(LL * DD));
}

// round 6
// speedup vs baseline: 2.2911x; 1.2225x over previous
#include <cuda_runtime.h>
#include <cuda_bf16.h>
#include <math.h>
#include <stdint.h>

// Problem constants
#define BB 4
#define LL 1024
#define DD 768
#define EE 32
#define SS 32
#define HH 3072
#define KK 1024   // E*S

// ---------------- device scratch ----------------
__device__ float g_xn[BB * LL * DD];
__device__ float g_phin[DD * KK];
__device__ float g_logits[BB * LL * KK];
__device__ float g_dw[BB * LL * KK];
__device__ float g_cw[BB * LL * KK];
__device__ float g_slots[BB * KK * DD];
__device__ float g_h[BB * KK * HH];
__device__ float g_eo[BB * KK * DD];

// ---------------- bf16 helpers ----------------
__device__ __forceinline__ void split_bf16_pack(float x0, float x1, unsigned& hi, unsigned& lo) {
    __nv_bfloat16 h0 = __float2bfloat16_rn(x0);
    __nv_bfloat16 l0 = __float2bfloat16_rn(x0 - __bfloat162float(h0));
    __nv_bfloat16 h1 = __float2bfloat16_rn(x1);
    __nv_bfloat16 l1 = __float2bfloat16_rn(x1 - __bfloat162float(h1));
    hi = ((unsigned)__bfloat16_as_ushort(h1) << 16) | (unsigned)__bfloat16_as_ushort(h0);
    lo = ((unsigned)__bfloat16_as_ushort(l1) << 16) | (unsigned)__bfloat16_as_ushort(l0);
}

__device__ __forceinline__ void mma_bf16(float* d, const unsigned* a, const unsigned* b) {
    asm volatile(
        "mma.sync.aligned.m16n8k16.row.col.f32.bf16.bf16.f32 "
        "{%0,%1,%2,%3}, {%4,%5,%6,%7}, {%8,%9}, {%0,%1,%2,%3};\n"
        : "+f"(d[0]), "+f"(d[1]), "+f"(d[2]), "+f"(d[3])
        : "r"(a[0]), "r"(a[1]), "r"(a[2]), "r"(a[3]), "r"(b[0]), "r"(b[1]));
}

__device__ __forceinline__ void ldsm_x4(unsigned* r, uint32_t a) {
    asm volatile("ldmatrix.sync.aligned.m8n8.x4.shared.b16 {%0,%1,%2,%3}, [%4];"
                 : "=r"(r[0]), "=r"(r[1]), "=r"(r[2]), "=r"(r[3]) : "r"(a));
}
__device__ __forceinline__ void ldsm_x2_trans(unsigned* r, uint32_t a) {
    asm volatile("ldmatrix.sync.aligned.m8n8.x2.trans.shared.b16 {%0,%1}, [%2];"
                 : "=r"(r[0]), "=r"(r[1]) : "r"(a));
}

__device__ __forceinline__ uint32_t smem_u32(const void* p) {
    return (uint32_t)__cvta_generic_to_shared(p);
}

// ---------------- norm / softmax ----------------
__global__ void norm_x_kernel(const float* __restrict__ x, float* __restrict__ out) {
    int row = blockIdx.x;
    const float* p = x + (size_t)row * DD;
    float s = 0.f;
    for (int i = threadIdx.x; i < DD; i += 256) { float v = p[i]; s += v * v; }
    __shared__ float sm[8];
    for (int o = 16; o; o >>= 1) s += __shfl_xor_sync(0xffffffffu, s, o);
    if ((threadIdx.x & 31) == 0) sm[threadIdx.x >> 5] = s;
    __syncthreads();
    float tot = 0.f;
#pragma unroll
    for (int i = 0; i < 8; i++) tot += sm[i];
    float inv = 1.f / fmaxf(sqrtf(tot), 1e-12f);
    float* o2 = out + (size_t)row * DD;
    for (int i = threadIdx.x; i < DD; i += 256) o2[i] = p[i] * inv;
}

__global__ void norm_phi_kernel(const float* __restrict__ phi,
                                const float* __restrict__ scale,
                                float* __restrict__ out) {
    int k = blockIdx.x;
    float s = 0.f;
    for (int d = threadIdx.x; d < DD; d += 256) { float v = phi[(size_t)d * KK + k]; s += v * v; }
    __shared__ float sm[8];
    for (int o = 16; o; o >>= 1) s += __shfl_xor_sync(0xffffffffu, s, o);
    if ((threadIdx.x & 31) == 0) sm[threadIdx.x >> 5] = s;
    __syncthreads();
    float tot = 0.f;
#pragma unroll
    for (int i = 0; i < 8; i++) tot += sm[i];
    float inv = scale[0] / fmaxf(sqrtf(tot), 1e-12f);
    for (int d = threadIdx.x; d < DD; d += 256) out[(size_t)d * KK + k] = phi[(size_t)d * KK + k] * inv;
}

__global__ void softmax_kernel(const float* __restrict__ logits,
                               float* __restrict__ dw, float* __restrict__ cw) {
    int row = blockIdx.x;
    size_t base = (size_t)row * KK;
    int tid = threadIdx.x, lane = tid & 31, wid = tid >> 5;
    float v = logits[base + tid];
    float gmax = v;
    for (int o = 16; o; o >>= 1) gmax = fmaxf(gmax, __shfl_xor_sync(0xffffffffu, gmax, o));
    float ge = expf(v - gmax);
    float gsum = ge;
    for (int o = 16; o; o >>= 1) gsum += __shfl_xor_sync(0xffffffffu, gsum, o);
    dw[base + tid] = ge / gsum;
    __shared__ float wmax[32], wsum[32];
    __shared__ float s_rmax, s_rsum;
    if (lane == 0) wmax[wid] = gmax;
    __syncthreads();
    if (tid < 32) {
        float m = wmax[tid];
        for (int o = 16; o; o >>= 1) m = fmaxf(m, __shfl_xor_sync(0xffffffffu, m, o));
        if (tid == 0) s_rmax = m;
    }
    __syncthreads();
    float e2 = expf(v - s_rmax);
    float ws = e2;
    for (int o = 16; o; o >>= 1) ws += __shfl_xor_sync(0xffffffffu, ws, o);
    if (lane == 0) wsum[wid] = ws;
    __syncthreads();
    if (tid < 32) {
        float t = wsum[tid];
        for (int o = 16; o; o >>= 1) t += __shfl_xor_sync(0xffffffffu, t, o);
        if (tid == 0) s_rsum = t;
    }
    __syncthreads();
    cw[base + tid] = e2 / s_rsum;
}

// ============ bf16x3 GEMM with ldmatrix, double-buffered, 128x128, Ktile=32 ==
// Smem per buffer (32KB): Ah[128 rows][64B] +0, Al +8192, Bh[32 k][256B] +16384,
// Bl +24576. A rows: m-major, 16B-chunk swizzle sel=(m>>1)&3. B rows: k-major,
// chunk swizzle sel=(k&7). Buffers at 0 / 32768. Total dynamic smem 64KB.
#define GSMEM_BYTES 65536

template <bool AKMAJ>
__global__ void __launch_bounds__(256) bf16_ldsm_gemm(
    const float* __restrict__ A, const float* __restrict__ B, float* __restrict__ C,
    int M, int N, int K,
    long sAm, long sAk, long batchA,
    long sBk, long batchB, long batchC) {
    extern __shared__ char smemraw[];
    uint32_t sbase = smem_u32(smemraw);
    const float* Ab = A + (size_t)blockIdx.z * batchA;
    const float* Bb = B + (size_t)blockIdx.z * batchB;
    float* Cb = C + (size_t)blockIdx.z * batchC;
    int m0 = blockIdx.y * 128, n0 = blockIdx.x * 128;
    int tid = threadIdx.x, lane = tid & 31, wid = tid >> 5;
    int warp_m = wid >> 2, warp_n = wid & 3;
    int g = lane >> 2, tig = lane & 3;
    // ldmatrix lane constants
    int mi = lane >> 3, lr = lane & 7;
    int aRow0 = warp_m * 64 + (mi & 1) * 8 + lr;
    int aSel = (aRow0 >> 1) & 3;
    int aKbH = mi >> 1;
    int bmi = mi & 1;

    float acc[4][4][4];
#pragma unroll
    for (int a = 0; a < 4; a++)
#pragma unroll
        for (int b = 0; b < 4; b++)
#pragma unroll
            for (int c = 0; c < 4; c++) acc[a][b][c] = 0.f;

    float4 vA[4], vB[4];
    float pA0[8], pA1[8];

    auto loadA = [&](int k0) {
        if (AKMAJ) {
#pragma unroll
            for (int i = 0; i < 4; i++) {
                int idx = i * 256 + tid;
                int m = idx >> 3, q = idx & 7;
                vA[i] = *(const float4*)&Ab[(size_t)(m0 + m) * sAm + (k0 + q * 4)];
            }
        } else {
#pragma unroll
            for (int i = 0; i < 8; i++) {
                int idx = i * 256 + tid;
                int m = idx & 127, k2 = idx >> 7;
                size_t o = (size_t)(m0 + m) * sAm + (size_t)(k0 + 2 * k2) * sAk;
                pA0[i] = Ab[o]; pA1[i] = Ab[o + sAk];
            }
        }
    };
    auto loadB = [&](int k0) {
#pragma unroll
        for (int i = 0; i < 4; i++) {
            int idx = i * 256 + tid;
            int n4 = idx & 31, kr = idx >> 5;
            vB[i] = *(const float4*)&Bb[(size_t)(k0 + kr) * sBk + (n0 + n4 * 4)];
        }
    };
    auto storeAB = [&](char* buf) {
        if (AKMAJ) {
#pragma unroll
            for (int i = 0; i < 4; i++) {
                int idx = i * 256 + tid;
                int m = idx >> 3, q = idx & 7;
                unsigned h0, l0, h1, l1;
                split_bf16_pack(vA[i].x, vA[i].y, h0, l0);
                split_bf16_pack(vA[i].z, vA[i].w, h1, l1);
                uint32_t off = m * 64 + (((q >> 1) ^ ((m >> 1) & 3)) << 4) + (q & 1) * 8;
                *(uint2*)(buf + off) = make_uint2(h0, h1);
                *(uint2*)(buf + 8192 + off) = make_uint2(l0, l1);
            }
        } else {
#pragma unroll
            for (int i = 0; i < 8; i++) {
                int idx = i * 256 + tid;
                int m = idx & 127, k2 = idx >> 7;
                unsigned h, l;
                split_bf16_pack(pA0[i], pA1[i], h, l);
                uint32_t off = m * 64 + (((k2 >> 2) ^ ((m >> 1) & 3)) << 4) + (k2 & 3) * 4;
                *(unsigned*)(buf + off) = h;
                *(unsigned*)(buf + 8192 + off) = l;
            }
        }
#pragma unroll
        for (int i = 0; i < 4; i++) {
            int idx = i * 256 + tid;
            int n4 = idx & 31, kr = idx >> 5;
            unsigned h0, l0, h1, l1;
            split_bf16_pack(vB[i].x, vB[i].y, h0, l0);
            split_bf16_pack(vB[i].z, vB[i].w, h1, l1);
            uint32_t off = kr * 256 + (((n4 >> 1) ^ (kr & 7)) << 4) + (n4 & 1) * 8;
            *(uint2*)(buf + 16384 + off) = make_uint2(h0, h1);
            *(uint2*)(buf + 24576 + off) = make_uint2(l0, l1);
        }
    };
    auto mmaTile = [&](uint32_t bb) {
#pragma unroll
        for (int ks = 0; ks < 2; ks++) {
            unsigned aHi[4][4], aLo[4][4], bHi[4][2], bLo[4][2];
#pragma unroll
            for (int mt = 0; mt < 4; mt++) {
                uint32_t ad = bb + (uint32_t)((aRow0 + mt * 16) * 64 +
                              (((ks * 2 + aKbH) ^ aSel) << 4));
                ldsm_x4(aHi[mt], ad);
                ldsm_x4(aLo[mt], ad + 8192);
            }
#pragma unroll
            for (int nt = 0; nt < 4; nt++) {
                int kr = ks * 16 + bmi * 8 + lr;
                uint32_t bd = bb + 16384 + (uint32_t)(kr * 256 +
                              (((warp_n * 4 + nt) ^ (kr & 7)) << 4));
                ldsm_x2_trans(bHi[nt], bd);
                ldsm_x2_trans(bLo[nt], bd + 8192);
            }
#pragma unroll
            for (int mt = 0; mt < 4; mt++)
#pragma unroll
                for (int nt = 0; nt < 4; nt++) {
                    mma_bf16(acc[mt][nt], aHi[mt], bLo[nt]);
                    mma_bf16(acc[mt][nt], aLo[mt], bHi[nt]);
                    mma_bf16(acc[mt][nt], aHi[mt], bHi[nt]);
                }
        }
    };

    int KT = K >> 5;
    loadA(0); loadB(0);
    storeAB(smemraw);
    __syncthreads();
    for (int kt = 0; kt < KT; kt++) {
        bool hn = (kt + 1) < KT;
        if (hn) { loadA((kt + 1) << 5); loadB((kt + 1) << 5); }
        mmaTile(sbase + (uint32_t)(kt & 1) * 32768);
        if (hn) storeAB(smemraw + ((kt + 1) & 1) * 32768);
        __syncthreads();
    }

#pragma unroll
    for (int mt = 0; mt < 4; mt++)
#pragma unroll
        for (int nt = 0; nt < 4; nt++) {
            int r = m0 + warp_m * 64 + mt * 16 + g;
            int c = n0 + warp_n * 32 + nt * 8 + tig * 2;
            *(float2*)&Cb[(size_t)r * N + c] = make_float2(acc[mt][nt][0], acc[mt][nt][1]);
            *(float2*)&Cb[(size_t)(r + 8) * N + c] = make_float2(acc[mt][nt][2], acc[mt][nt][3]);
        }
}

// ---- expert variant: gathered A/C rows, per-expert B + bias (+GELU) ---------
template <bool GELU>
__global__ void __launch_bounds__(256) bf16_ldsm_expert(
    const float* __restrict__ A, const float* __restrict__ B,
    const float* __restrict__ bias, float* __restrict__ C,
    int N, int K, long aBatch, long cBatch) {
    extern __shared__ char smemraw[];
    uint32_t sbase = smem_u32(smemraw);
    int e = blockIdx.z;
    const float* Be = B + (size_t)e * (size_t)K * N;
    const float* biasE = bias + (size_t)e * N;
    int n0 = blockIdx.x * 128;
    int tid = threadIdx.x, lane = tid & 31, wid = tid >> 5;
    int warp_m = wid >> 2, warp_n = wid & 3;
    int g = lane >> 2, tig = lane & 3;
    int mi = lane >> 3, lr = lane & 7;
    int aRow0 = warp_m * 64 + (mi & 1) * 8 + lr;
    int aSel = (aRow0 >> 1) & 3;
    int aKbH = mi >> 1;
    int bmi = mi & 1;

    float acc[4][4][4];
#pragma unroll
    for (int a = 0; a < 4; a++)
#pragma unroll
        for (int b = 0; b < 4; b++)
#pragma unroll
            for (int c = 0; c < 4; c++) acc[a][b][c] = 0.f;

    float4 vA[4], vB[4];

    auto loadA = [&](int k0) {
#pragma unroll
        for (int i = 0; i < 4; i++) {
            int idx = i * 256 + tid;
            int m = idx >> 3, q = idx & 7;
            size_t off = (size_t)(m >> 5) * aBatch + (size_t)(e * 32 + (m & 31)) * K;
            vA[i] = *(const float4*)&A[off + k0 + q * 4];
        }
    };
    auto loadB = [&](int k0) {
#pragma unroll
        for (int i = 0; i < 4; i++) {
            int idx = i * 256 + tid;
            int n4 = idx & 31, kr = idx >> 5;
            vB[i] = *(const float4*)&Be[(size_t)(k0 + kr) * N + (n0 + n4 * 4)];
        }
    };
    auto storeAB = [&](char* buf) {
#pragma unroll
        for (int i = 0; i < 4; i++) {
            int idx = i * 256 + tid;
            int m = idx >> 3, q = idx & 7;
            unsigned h0, l0, h1, l1;
            split_bf16_pack(vA[i].x, vA[i].y, h0, l0);
            split_bf16_pack(vA[i].z, vA[i].w, h1, l1);
            uint32_t off = m * 64 + (((q >> 1) ^ ((m >> 1) & 3)) << 4) + (q & 1) * 8;
            *(uint2*)(buf + off) = make_uint2(h0, h1);
            *(uint2*)(buf + 8192 + off) = make_uint2(l0, l1);
        }
#pragma unroll
        for (int i = 0; i < 4; i++) {
            int idx = i * 256 + tid;
            int n4 = idx & 31, kr = idx >> 5;
            unsigned h0, l0, h1, l1;
            split_bf16_pack(vB[i].x, vB[i].y, h0, l0);
            split_bf16_pack(vB[i].z, vB[i].w, h1, l1);
            uint32_t off = kr * 256 + (((n4 >> 1) ^ (kr & 7)) << 4) + (n4 & 1) * 8;
            *(uint2*)(buf + 16384 + off) = make_uint2(h0, h1);
            *(uint2*)(buf + 24576 + off) = make_uint2(l0, l1);
        }
    };
    auto mmaTile = [&](uint32_t bb) {
#pragma unroll
        for (int ks = 0; ks < 2; ks++) {
            unsigned aHi[4][4], aLo[4][4], bHi[4][2], bLo[4][2];
#pragma unroll
            for (int mt = 0; mt < 4; mt++) {
                uint32_t ad = bb + (uint32_t)((aRow0 + mt * 16) * 64 +
                              (((ks * 2 + aKbH) ^ aSel) << 4));
                ldsm_x4(aHi[mt], ad);
                ldsm_x4(aLo[mt], ad + 8192);
            }
#pragma unroll
            for (int nt = 0; nt < 4; nt++) {
                int kr = ks * 16 + bmi * 8 + lr;
                uint32_t bd = bb + 16384 + (uint32_t)(kr * 256 +
                              (((warp_n * 4 + nt) ^ (kr & 7)) << 4));
                ldsm_x2_trans(bHi[nt], bd);
                ldsm_x2_trans(bLo[nt], bd + 8192);
            }
#pragma unroll
            for (int mt = 0; mt < 4; mt++)
#pragma unroll
                for (int nt = 0; nt < 4; nt++) {
                    mma_bf16(acc[mt][nt], aHi[mt], bLo[nt]);
                    mma_bf16(acc[mt][nt], aLo[mt], bHi[nt]);
                    mma_bf16(acc[mt][nt], aHi[mt], bHi[nt]);
                }
        }
    };

    int KT = K >> 5;
    loadA(0); loadB(0);
    storeAB(smemraw);
    __syncthreads();
    for (int kt = 0; kt < KT; kt++) {
        bool hn = (kt + 1) < KT;
        if (hn) { loadA((kt + 1) << 5); loadB((kt + 1) << 5); }
        mmaTile(sbase + (uint32_t)(kt & 1) * 32768);
        if (hn) storeAB(smemraw + ((kt + 1) & 1) * 32768);
        __syncthreads();
    }

#pragma unroll
    for (int mt = 0; mt < 4; mt++)
#pragma unroll
        for (int nt = 0; nt < 4; nt++) {
            int m = warp_m * 64 + mt * 16 + g;
            int c = n0 + warp_n * 32 + nt * 8 + tig * 2;
            float2 bb = *(const float2*)&biasE[c];
#pragma unroll
            for (int half = 0; half < 2; half++) {
                int mm = m + half * 8;
                size_t coff = (size_t)(mm >> 5) * cBatch + (size_t)(e * 32 + (mm & 31)) * N;
                float v0 = acc[mt][nt][half * 2 + 0] + bb.x;
                float v1 = acc[mt][nt][half * 2 + 1] + bb.y;
                if (GELU) { v0 = v0 * normcdff(v0); v1 = v1 * normcdff(v1); }
                *(float2*)&C[coff + c] = make_float2(v0, v1);
            }
        }
}

// ---------------- host launcher ----------------
extern "C" void kernel_launch(void* const* d_in, const int* in_sizes, int n_in,
                              void* d_out, int out_size) {
    const float* x     = (const float*)d_in[0];
    const float* phi   = (const float*)d_in[1];
    const float* scale = (const float*)d_in[2];
    const float* w1    = (const float*)d_in[3];
    const float* b1    = (const float*)d_in[4];
    const float* w2    = (const float*)d_in[5];
    const float* b2    = (const float*)d_in[6];
    float* out = (float*)d_out;

    float *xn, *phin, *logits, *dw, *cw, *slots, *h, *eo;
    cudaGetSymbolAddress((void**)&xn, g_xn);
    cudaGetSymbolAddress((void**)&phin, g_phin);
    cudaGetSymbolAddress((void**)&logits, g_logits);
    cudaGetSymbolAddress((void**)&dw, g_dw);
    cudaGetSymbolAddress((void**)&cw, g_cw);
    cudaGetSymbolAddress((void**)&slots, g_slots);
    cudaGetSymbolAddress((void**)&h, g_h);
    cudaGetSymbolAddress((void**)&eo, g_eo);

    cudaFuncSetAttribute(bf16_ldsm_gemm<true>,
                         cudaFuncAttributeMaxDynamicSharedMemorySize, GSMEM_BYTES);
    cudaFuncSetAttribute(bf16_ldsm_gemm<false>,
                         cudaFuncAttributeMaxDynamicSharedMemorySize, GSMEM_BYTES);
    cudaFuncSetAttribute(bf16_ldsm_expert<true>,
                         cudaFuncAttributeMaxDynamicSharedMemorySize, GSMEM_BYTES);
    cudaFuncSetAttribute(bf16_ldsm_expert<false>,
                         cudaFuncAttributeMaxDynamicSharedMemorySize, GSMEM_BYTES);

    // 1) normalize x rows -> xn [4096,768]
    norm_x_kernel<<<BB * LL, 256>>>(x, xn);
    // 2) normalize phi columns * scale -> phin [768,1024]
    norm_phi_kernel<<<KK, 256>>>(phi, scale, phin);
    // 3) logits [4096,1024] = xn @ phin  (A k-major)
    bf16_ldsm_gemm<true><<<dim3(KK / 128, (BB * LL) / 128, 1), 256, GSMEM_BYTES>>>(
        xn, phin, logits, BB * LL, KK, DD,
        (long)DD, 1L, 0L,
        (long)KK, 0L, 0L);
    // 4) softmaxes
    softmax_kernel<<<BB * LL, 1024>>>(logits, dw, cw);
    // 5) slots[b] [1024,768] = dw[b]^T @ xn[b]  (A m-major)
    bf16_ldsm_gemm<false><<<dim3(DD / 128, KK / 128, BB), 256, GSMEM_BYTES>>>(
        dw, xn, slots, KK, DD, LL,
        1L, (long)KK, (long)(LL * KK),
        (long)DD, (long)(LL * DD), (long)(KK * DD));
    // 6) h = gelu(slots @ w1 + b1)
    bf16_ldsm_expert<true><<<dim3(HH / 128, 1, EE), 256, GSMEM_BYTES>>>(
        slots, w1, b1, h, HH, DD, (long)(KK * DD), (long)(KK * HH));
    // 7) eo = h @ w2 + b2
    bf16_ldsm_expert<false><<<dim3(DD / 128, 1, EE), 256, GSMEM_BYTES>>>(
        h, w2, b2, eo, DD, HH, (long)(KK * HH), (long)(KK * DD));
    // 8) out[b] [1024,768] = cw[b] @ eo[b]  (A k-major)
    bf16_ldsm_gemm<true><<<dim3(DD / 128, LL / 128, BB), 256, GSMEM_BYTES>>>(
        cw, eo, out, LL, DD, KK,
        (long)KK, 1L, (long)(LL * KK),
        (long)DD, (long)(KK * DD), (long)(LL * DD));
}

// round 7
// speedup vs baseline: 2.8552x; 1.2462x over previous
#include <cuda_runtime.h>
#include <cuda_bf16.h>
#include <math.h>
#include <stdint.h>

// Problem constants
#define BB 4
#define LL 1024
#define DD 768
#define EE 32
#define SS 32
#define HH 3072
#define KK 1024   // E*S

// ---------------- device scratch ----------------
__device__ float g_xn[BB * LL * DD];
__device__ float g_phin[DD * KK];
__device__ float g_logits[BB * LL * KK];
__device__ float g_dw[BB * LL * KK];
__device__ float g_cw[BB * LL * KK];
__device__ float g_slots[BB * KK * DD];
__device__ float g_h[BB * KK * HH];
__device__ float g_eo[BB * KK * DD];

// ---------------- bf16 helpers ----------------
__device__ __forceinline__ void split_bf16_pack(float x0, float x1, unsigned& hi, unsigned& lo) {
    __nv_bfloat16 h0 = __float2bfloat16_rn(x0);
    __nv_bfloat16 l0 = __float2bfloat16_rn(x0 - __bfloat162float(h0));
    __nv_bfloat16 h1 = __float2bfloat16_rn(x1);
    __nv_bfloat16 l1 = __float2bfloat16_rn(x1 - __bfloat162float(h1));
    hi = ((unsigned)__bfloat16_as_ushort(h1) << 16) | (unsigned)__bfloat16_as_ushort(h0);
    lo = ((unsigned)__bfloat16_as_ushort(l1) << 16) | (unsigned)__bfloat16_as_ushort(l0);
}

__device__ __forceinline__ void mma_bf16(float* d, const unsigned* a, const unsigned* b) {
    asm volatile(
        "mma.sync.aligned.m16n8k16.row.col.f32.bf16.bf16.f32 "
        "{%0,%1,%2,%3}, {%4,%5,%6,%7}, {%8,%9}, {%0,%1,%2,%3};\n"
        : "+f"(d[0]), "+f"(d[1]), "+f"(d[2]), "+f"(d[3])
        : "r"(a[0]), "r"(a[1]), "r"(a[2]), "r"(a[3]), "r"(b[0]), "r"(b[1]));
}

__device__ __forceinline__ void ldsm_x4(unsigned* r, uint32_t a) {
    asm volatile("ldmatrix.sync.aligned.m8n8.x4.shared.b16 {%0,%1,%2,%3}, [%4];"
                 : "=r"(r[0]), "=r"(r[1]), "=r"(r[2]), "=r"(r[3]) : "r"(a));
}
__device__ __forceinline__ void ldsm_x2_trans(unsigned* r, uint32_t a) {
    asm volatile("ldmatrix.sync.aligned.m8n8.x2.trans.shared.b16 {%0,%1}, [%2];"
                 : "=r"(r[0]), "=r"(r[1]) : "r"(a));
}

__device__ __forceinline__ uint32_t smem_u32(const void* p) {
    return (uint32_t)__cvta_generic_to_shared(p);
}

// ---------------- norm / softmax ----------------
__global__ void norm_x_kernel(const float* __restrict__ x, float* __restrict__ out) {
    int row = blockIdx.x;
    const float* p = x + (size_t)row * DD;
    float s = 0.f;
    for (int i = threadIdx.x; i < DD; i += 256) { float v = p[i]; s += v * v; }
    __shared__ float sm[8];
    for (int o = 16; o; o >>= 1) s += __shfl_xor_sync(0xffffffffu, s, o);
    if ((threadIdx.x & 31) == 0) sm[threadIdx.x >> 5] = s;
    __syncthreads();
    float tot = 0.f;
#pragma unroll
    for (int i = 0; i < 8; i++) tot += sm[i];
    float inv = 1.f / fmaxf(sqrtf(tot), 1e-12f);
    float* o2 = out + (size_t)row * DD;
    for (int i = threadIdx.x; i < DD; i += 256) o2[i] = p[i] * inv;
}

__global__ void norm_phi_kernel(const float* __restrict__ phi,
                                const float* __restrict__ scale,
                                float* __restrict__ out) {
    int k = blockIdx.x;
    float s = 0.f;
    for (int d = threadIdx.x; d < DD; d += 256) { float v = phi[(size_t)d * KK + k]; s += v * v; }
    __shared__ float sm[8];
    for (int o = 16; o; o >>= 1) s += __shfl_xor_sync(0xffffffffu, s, o);
    if ((threadIdx.x & 31) == 0) sm[threadIdx.x >> 5] = s;
    __syncthreads();
    float tot = 0.f;
#pragma unroll
    for (int i = 0; i < 8; i++) tot += sm[i];
    float inv = scale[0] / fmaxf(sqrtf(tot), 1e-12f);
    for (int d = threadIdx.x; d < DD; d += 256) out[(size_t)d * KK + k] = phi[(size_t)d * KK + k] * inv;
}

__global__ void softmax_kernel(const float* __restrict__ logits,
                               float* __restrict__ dw, float* __restrict__ cw) {
    int row = blockIdx.x;
    size_t base = (size_t)row * KK;
    int tid = threadIdx.x, lane = tid & 31, wid = tid >> 5;
    float v = logits[base + tid];
    float gmax = v;
    for (int o = 16; o; o >>= 1) gmax = fmaxf(gmax, __shfl_xor_sync(0xffffffffu, gmax, o));
    float ge = expf(v - gmax);
    float gsum = ge;
    for (int o = 16; o; o >>= 1) gsum += __shfl_xor_sync(0xffffffffu, gsum, o);
    dw[base + tid] = ge / gsum;
    __shared__ float wmax[32], wsum[32];
    __shared__ float s_rmax, s_rsum;
    if (lane == 0) wmax[wid] = gmax;
    __syncthreads();
    if (tid < 32) {
        float m = wmax[tid];
        for (int o = 16; o; o >>= 1) m = fmaxf(m, __shfl_xor_sync(0xffffffffu, m, o));
        if (tid == 0) s_rmax = m;
    }
    __syncthreads();
    float e2 = expf(v - s_rmax);
    float ws = e2;
    for (int o = 16; o; o >>= 1) ws += __shfl_xor_sync(0xffffffffu, ws, o);
    if (lane == 0) wsum[wid] = ws;
    __syncthreads();
    if (tid < 32) {
        float t = wsum[tid];
        for (int o = 16; o; o >>= 1) t += __shfl_xor_sync(0xffffffffu, t, o);
        if (tid == 0) s_rsum = t;
    }
    __syncthreads();
    cw[base + tid] = e2 / s_rsum;
}

// ============ bf16x3 GEMM with ldmatrix, double-buffered, 128x128, Ktile=32 ==
// 2 CTAs/SM target: __launch_bounds__(256,2), 64KB smem each.
#define GSMEM_BYTES 65536

template <bool AKMAJ>
__global__ void __launch_bounds__(256, 2) bf16_ldsm_gemm(
    const float* __restrict__ A, const float* __restrict__ B, float* __restrict__ C,
    int M, int N, int K,
    long sAm, long sAk, long batchA,
    long sBk, long batchB, long batchC) {
    extern __shared__ char smemraw[];
    uint32_t sbase = smem_u32(smemraw);
    const float* Ab = A + (size_t)blockIdx.z * batchA;
    const float* Bb = B + (size_t)blockIdx.z * batchB;
    float* Cb = C + (size_t)blockIdx.z * batchC;
    int m0 = blockIdx.y * 128, n0 = blockIdx.x * 128;
    int tid = threadIdx.x, lane = tid & 31, wid = tid >> 5;
    int warp_m = wid >> 2, warp_n = wid & 3;
    int g = lane >> 2, tig = lane & 3;
    int mi = lane >> 3, lr = lane & 7;
    int aRow0 = warp_m * 64 + (mi & 1) * 8 + lr;
    int aSel = (aRow0 >> 1) & 3;
    int aKbH = mi >> 1;
    int bmi = mi & 1;

    float acc[4][4][4];
#pragma unroll
    for (int a = 0; a < 4; a++)
#pragma unroll
        for (int b = 0; b < 4; b++)
#pragma unroll
            for (int c = 0; c < 4; c++) acc[a][b][c] = 0.f;

    auto loadStore = [&](int k0, char* buf) {
        if (AKMAJ) {
#pragma unroll
            for (int i = 0; i < 4; i++) {
                int idx = i * 256 + tid;
                int m = idx >> 3, q = idx & 7;
                float4 v = *(const float4*)&Ab[(size_t)(m0 + m) * sAm + (k0 + q * 4)];
                unsigned h0, l0, h1, l1;
                split_bf16_pack(v.x, v.y, h0, l0);
                split_bf16_pack(v.z, v.w, h1, l1);
                uint32_t off = m * 64 + (((q >> 1) ^ ((m >> 1) & 3)) << 4) + (q & 1) * 8;
                *(uint2*)(buf + off) = make_uint2(h0, h1);
                *(uint2*)(buf + 8192 + off) = make_uint2(l0, l1);
            }
        } else {
#pragma unroll
            for (int i = 0; i < 8; i++) {
                int idx = i * 256 + tid;
                int m = idx & 127, k2 = idx >> 7;
                size_t o = (size_t)(m0 + m) * sAm + (size_t)(k0 + 2 * k2) * sAk;
                float v0 = Ab[o], v1 = Ab[o + sAk];
                unsigned h, l;
                split_bf16_pack(v0, v1, h, l);
                uint32_t off = m * 64 + (((k2 >> 2) ^ ((m >> 1) & 3)) << 4) + (k2 & 3) * 4;
                *(unsigned*)(buf + off) = h;
                *(unsigned*)(buf + 8192 + off) = l;
            }
        }
#pragma unroll
        for (int i = 0; i < 4; i++) {
            int idx = i * 256 + tid;
            int n4 = idx & 31, kr = idx >> 5;
            float4 v = *(const float4*)&Bb[(size_t)(k0 + kr) * sBk + (n0 + n4 * 4)];
            unsigned h0, l0, h1, l1;
            split_bf16_pack(v.x, v.y, h0, l0);
            split_bf16_pack(v.z, v.w, h1, l1);
            uint32_t off = kr * 256 + (((n4 >> 1) ^ (kr & 7)) << 4) + (n4 & 1) * 8;
            *(uint2*)(buf + 16384 + off) = make_uint2(h0, h1);
            *(uint2*)(buf + 24576 + off) = make_uint2(l0, l1);
        }
    };
    auto mmaTile = [&](uint32_t bb) {
#pragma unroll
        for (int ks = 0; ks < 2; ks++) {
            unsigned bHi[4][2], bLo[4][2];
#pragma unroll
            for (int nt = 0; nt < 4; nt++) {
                int kr = ks * 16 + bmi * 8 + lr;
                uint32_t bd = bb + 16384 + (uint32_t)(kr * 256 +
                              (((warp_n * 4 + nt) ^ (kr & 7)) << 4));
                ldsm_x2_trans(bHi[nt], bd);
                ldsm_x2_trans(bLo[nt], bd + 8192);
            }
#pragma unroll
            for (int mt = 0; mt < 4; mt++) {
                unsigned aHi[4], aLo[4];
                uint32_t ad = bb + (uint32_t)((aRow0 + mt * 16) * 64 +
                              (((ks * 2 + aKbH) ^ aSel) << 4));
                ldsm_x4(aHi, ad);
                ldsm_x4(aLo, ad + 8192);
#pragma unroll
                for (int nt = 0; nt < 4; nt++) {
                    mma_bf16(acc[mt][nt], aHi, bLo[nt]);
                    mma_bf16(acc[mt][nt], aLo, bHi[nt]);
                    mma_bf16(acc[mt][nt], aHi, bHi[nt]);
                }
            }
        }
    };

    int KT = K >> 5;
    loadStore(0, smemraw);
    __syncthreads();
    for (int kt = 0; kt < KT; kt++) {
        mmaTile(sbase + (uint32_t)(kt & 1) * 32768);
        if (kt + 1 < KT) loadStore((kt + 1) << 5, smemraw + ((kt + 1) & 1) * 32768);
        __syncthreads();
    }

#pragma unroll
    for (int mt = 0; mt < 4; mt++)
#pragma unroll
        for (int nt = 0; nt < 4; nt++) {
            int r = m0 + warp_m * 64 + mt * 16 + g;
            int c = n0 + warp_n * 32 + nt * 8 + tig * 2;
            *(float2*)&Cb[(size_t)r * N + c] = make_float2(acc[mt][nt][0], acc[mt][nt][1]);
            *(float2*)&Cb[(size_t)(r + 8) * N + c] = make_float2(acc[mt][nt][2], acc[mt][nt][3]);
        }
}

// ---- expert variant: gathered A/C rows, per-expert B + bias (+GELU) ---------
template <bool GELU>
__global__ void __launch_bounds__(256, 2) bf16_ldsm_expert(
    const float* __restrict__ A, const float* __restrict__ B,
    const float* __restrict__ bias, float* __restrict__ C,
    int N, int K, long aBatch, long cBatch) {
    extern __shared__ char smemraw[];
    uint32_t sbase = smem_u32(smemraw);
    int e = blockIdx.z;
    const float* Be = B + (size_t)e * (size_t)K * N;
    const float* biasE = bias + (size_t)e * N;
    int n0 = blockIdx.x * 128;
    int tid = threadIdx.x, lane = tid & 31, wid = tid >> 5;
    int warp_m = wid >> 2, warp_n = wid & 3;
    int g = lane >> 2, tig = lane & 3;
    int mi = lane >> 3, lr = lane & 7;
    int aRow0 = warp_m * 64 + (mi & 1) * 8 + lr;
    int aSel = (aRow0 >> 1) & 3;
    int aKbH = mi >> 1;
    int bmi = mi & 1;

    float acc[4][4][4];
#pragma unroll
    for (int a = 0; a < 4; a++)
#pragma unroll
        for (int b = 0; b < 4; b++)
#pragma unroll
            for (int c = 0; c < 4; c++) acc[a][b][c] = 0.f;

    auto loadStore = [&](int k0, char* buf) {
#pragma unroll
        for (int i = 0; i < 4; i++) {
            int idx = i * 256 + tid;
            int m = idx >> 3, q = idx & 7;
            size_t off0 = (size_t)(m >> 5) * aBatch + (size_t)(e * 32 + (m & 31)) * K;
            float4 v = *(const float4*)&A[off0 + k0 + q * 4];
            unsigned h0, l0, h1, l1;
            split_bf16_pack(v.x, v.y, h0, l0);
            split_bf16_pack(v.z, v.w, h1, l1);
            uint32_t off = m * 64 + (((q >> 1) ^ ((m >> 1) & 3)) << 4) + (q & 1) * 8;
            *(uint2*)(buf + off) = make_uint2(h0, h1);
            *(uint2*)(buf + 8192 + off) = make_uint2(l0, l1);
        }
#pragma unroll
        for (int i = 0; i < 4; i++) {
            int idx = i * 256 + tid;
            int n4 = idx & 31, kr = idx >> 5;
            float4 v = *(const float4*)&Be[(size_t)(k0 + kr) * N + (n0 + n4 * 4)];
            unsigned h0, l0, h1, l1;
            split_bf16_pack(v.x, v.y, h0, l0);
            split_bf16_pack(v.z, v.w, h1, l1);
            uint32_t off = kr * 256 + (((n4 >> 1) ^ (kr & 7)) << 4) + (n4 & 1) * 8;
            *(uint2*)(buf + 16384 + off) = make_uint2(h0, h1);
            *(uint2*)(buf + 24576 + off) = make_uint2(l0, l1);
        }
    };
    auto mmaTile = [&](uint32_t bb) {
#pragma unroll
        for (int ks = 0; ks < 2; ks++) {
            unsigned bHi[4][2], bLo[4][2];
#pragma unroll
            for (int nt = 0; nt < 4; nt++) {
                int kr = ks * 16 + bmi * 8 + lr;
                uint32_t bd = bb + 16384 + (uint32_t)(kr * 256 +
                              (((warp_n * 4 + nt) ^ (kr & 7)) << 4));
                ldsm_x2_trans(bHi[nt], bd);
                ldsm_x2_trans(bLo[nt], bd + 8192);
            }
#pragma unroll
            for (int mt = 0; mt < 4; mt++) {
                unsigned aHi[4], aLo[4];
                uint32_t ad = bb + (uint32_t)((aRow0 + mt * 16) * 64 +
                              (((ks * 2 + aKbH) ^ aSel) << 4));
                ldsm_x4(aHi, ad);
                ldsm_x4(aLo, ad + 8192);
#pragma unroll
                for (int nt = 0; nt < 4; nt++) {
                    mma_bf16(acc[mt][nt], aHi, bLo[nt]);
                    mma_bf16(acc[mt][nt], aLo, bHi[nt]);
                    mma_bf16(acc[mt][nt], aHi, bHi[nt]);
                }
            }
        }
    };

    int KT = K >> 5;
    loadStore(0, smemraw);
    __syncthreads();
    for (int kt = 0; kt < KT; kt++) {
        mmaTile(sbase + (uint32_t)(kt & 1) * 32768);
        if (kt + 1 < KT) loadStore((kt + 1) << 5, smemraw + ((kt + 1) & 1) * 32768);
        __syncthreads();
    }

#pragma unroll
    for (int mt = 0; mt < 4; mt++)
#pragma unroll
        for (int nt = 0; nt < 4; nt++) {
            int m = warp_m * 64 + mt * 16 + g;
            int c = n0 + warp_n * 32 + nt * 8 + tig * 2;
            float2 bb = *(const float2*)&biasE[c];
#pragma unroll
            for (int half = 0; half < 2; half++) {
                int mm = m + half * 8;
                size_t coff = (size_t)(mm >> 5) * cBatch + (size_t)(e * 32 + (mm & 31)) * N;
                float v0 = acc[mt][nt][half * 2 + 0] + bb.x;
                float v1 = acc[mt][nt][half * 2 + 1] + bb.y;
                if (GELU) { v0 = v0 * normcdff(v0); v1 = v1 * normcdff(v1); }
                *(float2*)&C[coff + c] = make_float2(v0, v1);
            }
        }
}

// ---------------- host launcher ----------------
extern "C" void kernel_launch(void* const* d_in, const int* in_sizes, int n_in,
                              void* d_out, int out_size) {
    const float* x     = (const float*)d_in[0];
    const float* phi   = (const float*)d_in[1];
    const float* scale = (const float*)d_in[2];
    const float* w1    = (const float*)d_in[3];
    const float* b1    = (const float*)d_in[4];
    const float* w2    = (const float*)d_in[5];
    const float* b2    = (const float*)d_in[6];
    float* out = (float*)d_out;

    float *xn, *phin, *logits, *dw, *cw, *slots, *h, *eo;
    cudaGetSymbolAddress((void**)&xn, g_xn);
    cudaGetSymbolAddress((void**)&phin, g_phin);
    cudaGetSymbolAddress((void**)&logits, g_logits);
    cudaGetSymbolAddress((void**)&dw, g_dw);
    cudaGetSymbolAddress((void**)&cw, g_cw);
    cudaGetSymbolAddress((void**)&slots, g_slots);
    cudaGetSymbolAddress((void**)&h, g_h);
    cudaGetSymbolAddress((void**)&eo, g_eo);

    cudaFuncSetAttribute(bf16_ldsm_gemm<true>,
                         cudaFuncAttributeMaxDynamicSharedMemorySize, GSMEM_BYTES);
    cudaFuncSetAttribute(bf16_ldsm_gemm<false>,
                         cudaFuncAttributeMaxDynamicSharedMemorySize, GSMEM_BYTES);
    cudaFuncSetAttribute(bf16_ldsm_expert<true>,
                         cudaFuncAttributeMaxDynamicSharedMemorySize, GSMEM_BYTES);
    cudaFuncSetAttribute(bf16_ldsm_expert<false>,
                         cudaFuncAttributeMaxDynamicSharedMemorySize, GSMEM_BYTES);

    // 1) normalize x rows -> xn [4096,768]
    norm_x_kernel<<<BB * LL, 256>>>(x, xn);
    // 2) normalize phi columns * scale -> phin [768,1024]
    norm_phi_kernel<<<KK, 256>>>(phi, scale, phin);
    // 3) logits [4096,1024] = xn @ phin  (A k-major)
    bf16_ldsm_gemm<true><<<dim3(KK / 128, (BB * LL) / 128, 1), 256, GSMEM_BYTES>>>(
        xn, phin, logits, BB * LL, KK, DD,
        (long)DD, 1L, 0L,
        (long)KK, 0L, 0L);
    // 4) softmaxes
    softmax_kernel<<<BB * LL, 1024>>>(logits, dw, cw);
    // 5) slots[b] [1024,768] = dw[b]^T @ xn[b]  (A m-major)
    bf16_ldsm_gemm<false><<<dim3(DD / 128, KK / 128, BB), 256, GSMEM_BYTES>>>(
        dw, xn, slots, KK, DD, LL,
        1L, (long)KK, (long)(LL * KK),
        (long)DD, (long)(LL * DD), (long)(KK * DD));
    // 6) h = gelu(slots @ w1 + b1)
    bf16_ldsm_expert<true><<<dim3(HH / 128, 1, EE), 256, GSMEM_BYTES>>>(
        slots, w1, b1, h, HH, DD, (long)(KK * DD), (long)(KK * HH));
    // 7) eo = h @ w2 + b2
    bf16_ldsm_expert<false><<<dim3(DD / 128, 1, EE), 256, GSMEM_BYTES>>>(
        h, w2, b2, eo, DD, HH, (long)(KK * HH), (long)(KK * DD));
    // 8) out[b] [1024,768] = cw[b] @ eo[b]  (A k-major)
    bf16_ldsm_gemm<true><<<dim3(DD / 128, LL / 128, BB), 256, GSMEM_BYTES>>>(
        cw, eo, out, LL, DD, KK,
        (long)KK, 1L, (long)(LL * KK),
        (long)DD, (long)(KK * DD), (long)(LL * DD));
}